// round 12
// baseline (speedup 1.0000x reference)
#include <cuda_runtime.h>
#include <cuda_bf16.h>
#include <math.h>

// Problem constants
#define BB   64
#define TT   512
#define EE   256
#define HH   256
#define G4   1024
#define KK   10

// -------- device scratch ----------------------------------------------------
__device__ float g_pre[2u * 32768u * 1024u];          // [dir][t*64+b][4H]
__device__ float g_h[2u * 512u * 64u * 256u];         // [dir][t][b][h]
__device__ float g_logits[512u * 64u * 10u];          // [t][b][k]
__device__ unsigned g_barg[16 * 32];                  // per-group counters (128B apart)

__global__ void init_kernel() {
    int i = threadIdx.x;
    if (i < 16 * 32) g_barg[i] = 0u;
}
__global__ void dummy_kernel() {}

// -------- f32x2 helpers (operands naturally packed — no movs) ---------------
__device__ __forceinline__ void fma2(unsigned long long& d,
                                     unsigned long long a,
                                     unsigned long long b) {
    asm("fma.rn.f32x2 %0, %1, %2, %0;" : "+l"(d) : "l"(a), "l"(b));
}
__device__ __forceinline__ float2 up2(unsigned long long v) {
    float2 r;
    asm("mov.b64 {%0,%1}, %2;" : "=f"(r.x), "=f"(r.y) : "l"(v));
    return r;
}

// ---------------------------------------------------------------------------
// Kernel A: fused embedding-gather + GEMM (byte-identical to the 902us config)
// ---------------------------------------------------------------------------
__global__ void __launch_bounds__(256)
pregemm_kernel(const int* __restrict__ sent,
               const float* __restrict__ emb,
               const float* __restrict__ Wih_f,
               const float* __restrict__ b_f,
               const float* __restrict__ Wih_b,
               const float* __restrict__ b_b) {
    const int dir = blockIdx.z;
    const int n0  = blockIdx.x * 128;
    const int m0  = blockIdx.y * 128;
    const float* Wih  = dir ? Wih_b : Wih_f;
    const float* bias = dir ? b_b  : b_f;

    __shared__ float As[2][16][128];
    __shared__ float Bs[2][16][128];
    __shared__ int   toks[128];

    const int tid = threadIdx.x;
    if (tid < 128) {
        int m = m0 + tid;
        toks[tid] = sent[(m & 63) * TT + (m >> 6)];
    }
    __syncthreads();

    const int mA   = tid & 127;
    const int half = tid >> 7;
    const int ty   = tid >> 4;
    const int tx   = tid & 15;

    const float4* emb4 = (const float4*)emb;
    const float4* w4   = (const float4*)Wih;

    const size_t arow = (size_t)toks[mA] * 64;
    const size_t brow = (size_t)(n0 + mA) * 64;

    float acc[8][8];
#pragma unroll
    for (int i = 0; i < 8; ++i)
#pragma unroll
        for (int j = 0; j < 8; ++j) acc[i][j] = 0.f;

    float4 a0g = emb4[arow + half * 2 + 0];
    float4 a1g = emb4[arow + half * 2 + 1];
    float4 b0g = w4  [brow + half * 2 + 0];
    float4 b1g = w4  [brow + half * 2 + 1];

    int buf = 0;
    {
        const int kb = half * 8;
        As[0][kb+0][mA]=a0g.x; As[0][kb+1][mA]=a0g.y; As[0][kb+2][mA]=a0g.z; As[0][kb+3][mA]=a0g.w;
        As[0][kb+4][mA]=a1g.x; As[0][kb+5][mA]=a1g.y; As[0][kb+6][mA]=a1g.z; As[0][kb+7][mA]=a1g.w;
        Bs[0][kb+0][mA]=b0g.x; Bs[0][kb+1][mA]=b0g.y; Bs[0][kb+2][mA]=b0g.z; Bs[0][kb+3][mA]=b0g.w;
        Bs[0][kb+4][mA]=b1g.x; Bs[0][kb+5][mA]=b1g.y; Bs[0][kb+6][mA]=b1g.z; Bs[0][kb+7][mA]=b1g.w;
    }
    __syncthreads();

    for (int kc = 0; kc < 16; ++kc) {
        if (kc < 15) {
            const size_t kq = (size_t)(kc + 1) * 4 + half * 2;
            a0g = emb4[arow + kq];  a1g = emb4[arow + kq + 1];
            b0g = w4  [brow + kq];  b1g = w4  [brow + kq + 1];
        }
#pragma unroll
        for (int kk = 0; kk < 16; ++kk) {
            float4 aA = *(const float4*)&As[buf][kk][ty * 8];
            float4 aB = *(const float4*)&As[buf][kk][ty * 8 + 4];
            float4 bA = *(const float4*)&Bs[buf][kk][tx * 8];
            float4 bB = *(const float4*)&Bs[buf][kk][tx * 8 + 4];
            float av[8] = {aA.x, aA.y, aA.z, aA.w, aB.x, aB.y, aB.z, aB.w};
            float bv[8] = {bA.x, bA.y, bA.z, bA.w, bB.x, bB.y, bB.z, bB.w};
#pragma unroll
            for (int i = 0; i < 8; ++i)
#pragma unroll
                for (int j = 0; j < 8; ++j)
                    acc[i][j] += av[i] * bv[j];
        }
        if (kc < 15) {
            const int nb = buf ^ 1;
            const int kb = half * 8;
            As[nb][kb+0][mA]=a0g.x; As[nb][kb+1][mA]=a0g.y; As[nb][kb+2][mA]=a0g.z; As[nb][kb+3][mA]=a0g.w;
            As[nb][kb+4][mA]=a1g.x; As[nb][kb+5][mA]=a1g.y; As[nb][kb+6][mA]=a1g.z; As[nb][kb+7][mA]=a1g.w;
            Bs[nb][kb+0][mA]=b0g.x; Bs[nb][kb+1][mA]=b0g.y; Bs[nb][kb+2][mA]=b0g.z; Bs[nb][kb+3][mA]=b0g.w;
            Bs[nb][kb+4][mA]=b1g.x; Bs[nb][kb+5][mA]=b1g.y; Bs[nb][kb+6][mA]=b1g.z; Bs[nb][kb+7][mA]=b1g.w;
            __syncthreads();
            buf = nb;
        }
    }

    float4 bv0 = ((const float4*)bias)[(n0 >> 2) + tx * 2];
    float4 bv1 = ((const float4*)bias)[(n0 >> 2) + tx * 2 + 1];
    float4* out4 = (float4*)g_pre;
#pragma unroll
    for (int i = 0; i < 8; ++i) {
        const int m = m0 + ty * 8 + i;
        const size_t row = (size_t)dir * 32768 + m;
        float4 o0, o1;
        o0.x = acc[i][0] + bv0.x; o0.y = acc[i][1] + bv0.y;
        o0.z = acc[i][2] + bv0.z; o0.w = acc[i][3] + bv0.w;
        o1.x = acc[i][4] + bv1.x; o1.y = acc[i][5] + bv1.y;
        o1.z = acc[i][6] + bv1.z; o1.w = acc[i][7] + bv1.w;
        out4[row * 256 + (n0 >> 2) + tx * 2]     = o0;
        out4[row * 256 + (n0 >> 2) + tx * 2 + 1] = o1;
    }
}

// ---------------------------------------------------------------------------
// Kernel B: recurrence, non-cluster, register-resident weights, FFMA2-packed,
// PER-GROUP barriers (16 groups of 8 blocks; group = (dir, bgroup)).
// ---------------------------------------------------------------------------
#define SHP 264

__device__ __forceinline__ float fsigm(float x) {
    return __fdividef(1.f, 1.f + __expf(-x));
}
__device__ __forceinline__ float ftanh(float x) {
    float e = __expf(-2.f * fabsf(x));
    float r = __fdividef(1.f - e, 1.f + e);
    return copysignf(r, x);
}

__global__ void __launch_bounds__(256)
lstm_rec_kernel(const float* __restrict__ Whh_f,
                const float* __restrict__ Whh_b) {
    const int bid = blockIdx.x;
    const int dir = bid >> 6;
    const int ug  = (bid >> 3) & 7;     // unit group (32 units)
    const int bg  = bid & 7;            // batch group (8 batches)
    const int grp = dir * 8 + bg;       // sync group (8 blocks, all ug)
    const int tid = threadIdx.x;        // 256
    const int u   = tid >> 3;           // 0..31 local unit
    const int kq  = tid & 7;            // k-slice / epilogue batch
    const int hu  = ug * 32 + u;
    const int bglob = bg * 8 + kq;

    const float* Whh = dir ? Whh_b : Whh_f;

    __shared__ __align__(16) float sH[8 * SHP];

    // weights in registers, packed u64 pairs (loaded once)
    const ulonglong2* whh2 = (const ulonglong2*)Whh;
    ulonglong2 w[4][8];
#pragma unroll
    for (int g = 0; g < 4; ++g)
#pragma unroll
        for (int j = 0; j < 8; ++j)
            w[g][j] = whh2[((size_t)(g * 256 + hu)) * 64 + kq + j * 8];

    const float4* gh4 = (const float4*)g_h;
    volatile unsigned* bar = &g_barg[grp * 32];

    // g_pre prefetch for first step
    const int t0 = dir ? 511 : 0;
    size_t pb = ((size_t)dir * 32768 + (size_t)t0 * 64 + bglob) * 1024 + hu;
    float4 pr;
    pr.x = __ldcg(&g_pre[pb]);
    pr.y = __ldcg(&g_pre[pb + 256]);
    pr.z = __ldcg(&g_pre[pb + 512]);
    pr.w = __ldcg(&g_pre[pb + 768]);

    float c = 0.f;

    for (int it = 0; it < 512; ++it) {
        const int t = dir ? (511 - it) : it;

        // ---- stage h(prev) for this block's 8 batches into smem ----
        if (it == 0) {
            float4 z = make_float4(0.f, 0.f, 0.f, 0.f);
#pragma unroll
            for (int s = 0; s < 2; ++s) {
                int e = tid + s * 256;
                int b_ = e >> 6, q = e & 63;
                *(float4*)&sH[b_ * SHP + q * 4] = z;
            }
        } else {
            const int tp = dir ? (t + 1) : (t - 1);
            size_t base = (((size_t)(dir * 512 + tp)) * 64 + bg * 8) * 64;
#pragma unroll
            for (int s = 0; s < 2; ++s) {
                int e = tid + s * 256;
                int b_ = e >> 6, q = e & 63;
                *(float4*)&sH[b_ * SHP + q * 4] = __ldcg(&gh4[base + b_ * 64 + q]);
            }
        }
        __syncthreads();

        // prefetch next step's g_pre
        float4 prn;
        if (it < 511) {
            const int tn = dir ? (t - 1) : (t + 1);
            size_t pbn = ((size_t)dir * 32768 + (size_t)tn * 64 + bglob) * 1024 + hu;
            prn.x = __ldcg(&g_pre[pbn]);
            prn.y = __ldcg(&g_pre[pbn + 256]);
            prn.z = __ldcg(&g_pre[pbn + 512]);
            prn.w = __ldcg(&g_pre[pbn + 768]);
        }

        // ---- FFMA2 GEMV: acc2[g][b] += w[g][:] * h[b][:] (packed pairs) ----
        unsigned long long acc2[4][8];
#pragma unroll
        for (int g = 0; g < 4; ++g)
#pragma unroll
            for (int b = 0; b < 8; ++b) acc2[g][b] = 0ull;

        const float* hb = &sH[kq * 4];
#pragma unroll
        for (int j = 0; j < 8; ++j) {
#pragma unroll
            for (int b = 0; b < 8; ++b) {
                ulonglong2 h2 = *(const ulonglong2*)&hb[b * SHP + j * 32];
#pragma unroll
                for (int g = 0; g < 4; ++g) {
                    fma2(acc2[g][b], w[g][j].x, h2.x);
                    fma2(acc2[g][b], w[g][j].y, h2.y);
                }
            }
        }

        // ---- horizontal + reduce over 8 kq slices ----
        float accf[4][8];
#pragma unroll
        for (int g = 0; g < 4; ++g)
#pragma unroll
            for (int b = 0; b < 8; ++b) {
                float2 f2 = up2(acc2[g][b]);
                float v = f2.x + f2.y;
                v += __shfl_xor_sync(0xFFFFFFFFu, v, 1);
                v += __shfl_xor_sync(0xFFFFFFFFu, v, 2);
                v += __shfl_xor_sync(0xFFFFFFFFu, v, 4);
                accf[g][b] = v;
            }

        float s[4];
#pragma unroll
        for (int g = 0; g < 4; ++g) {
            float v = accf[g][0];
#pragma unroll
            for (int b = 1; b < 8; ++b) v = (kq == b) ? accf[g][b] : v;
            s[g] = v;
        }

        float gi = s[0] + pr.x;
        float gf = s[1] + pr.y;
        float gg = s[2] + pr.z;
        float go = s[3] + pr.w;

        float iv = fsigm(gi), fv = fsigm(gf), gv = ftanh(gg), ov = fsigm(go);
        c = fv * c + iv * gv;
        float hval = ov * ftanh(c);

        g_h[(((size_t)(dir * 512 + t)) * 64 + bglob) * 256 + hu] = hval;

        __syncthreads();

        if (it < 511) {
            if (tid == 0) {
                __threadfence();
                atomicAdd((unsigned*)bar, 1u);
                unsigned target = 8u * (unsigned)(it + 1);
                while (*bar < target) { }
            }
            __syncthreads();
            __threadfence();
        }
        pr = prn;
    }
}

// ---------------------------------------------------------------------------
// Kernel C: logits (unchanged)
// ---------------------------------------------------------------------------
__global__ void logits_kernel(const float* __restrict__ Wout,
                              const float* __restrict__ bout) {
    const int t = blockIdx.x;
    __shared__ float sWo[10 * 512];
    __shared__ float sCH[64 * 65];
    __shared__ float sBo[10];

    const int tid = threadIdx.x;      // 640
    for (int idx = tid; idx < 5120; idx += 640) sWo[idx] = Wout[idx];
    if (tid < 10) sBo[tid] = bout[tid];

    const int n = tid / 64, bb = tid & 63;
    float acc = 0.f;
    const float4* gh4 = (const float4*)g_h;

    for (int ch = 0; ch < 8; ++ch) {
        __syncthreads();
        for (int idx = tid; idx < 1024; idx += 640) {
            int b_ = idx >> 4, q = idx & 15;
            int d = ch >> 2;
            int hid4 = (ch & 3) * 16 + q;
            float4 v = gh4[(((size_t)d * 512 + t) * 64 + b_) * 64 + hid4];
            float* dst = &sCH[(q * 4) * 65 + b_];
            dst[0]   = v.x;  dst[65]  = v.y;
            dst[130] = v.z;  dst[195] = v.w;
        }
        __syncthreads();
#pragma unroll 8
        for (int r = 0; r < 64; ++r)
            acc += sWo[n * 512 + ch * 64 + r] * sCH[r * 65 + bb];
    }
    g_logits[((size_t)t * 64 + bb) * 10 + n] = acc + sBo[n];
}

// ---------------------------------------------------------------------------
// Kernel D: Viterbi (unchanged, 63us)
// ---------------------------------------------------------------------------
__global__ void viterbi_kernel(const float* __restrict__ trans,
                               float* __restrict__ out) {
    const int tid  = threadIdx.x;
    const int w    = tid >> 5;
    const int lane = tid & 31;
    const int b    = blockIdx.x * 4 + w;

    __shared__ float         sLT[2][16][4][10];
    __shared__ float         sCur[4][32];
    __shared__ unsigned char bp[4][512][10];
    __shared__ float         tr[100];

    for (int i = tid; i < 100; i += 128) tr[i] = trans[i];

    const int bbase = blockIdx.x * 4;
    float stage[5];
#pragma unroll
    for (int s = 0; s < 5; ++s) {
        int idx = tid + s * 128;
        int t_off = idx / 40, rem = idx % 40;
        int b_off = rem / 10, k = rem % 10;
        stage[s] = g_logits[((size_t)(0 + t_off) * 64 + bbase + b_off) * 10 + k];
    }
#pragma unroll
    for (int s = 0; s < 5; ++s) {
        int idx = tid + s * 128;
        int t_off = idx / 40, rem = idx % 40;
        int b_off = rem / 10, k = rem % 10;
        sLT[0][t_off][b_off][k] = stage[s];
    }
    __syncthreads();

    float trc[10];
#pragma unroll
    for (int i = 0; i < 10; ++i) trc[i] = (lane < 10) ? tr[i * 10 + lane] : 0.f;

    float cur = (lane < 10) ? sLT[0][0][w][lane] : -1e30f;

    for (int cchunk = 0; cchunk < 32; ++cchunk) {
        const int buf = cchunk & 1;
        if (cchunk < 31) {
            const int tb = (cchunk + 1) * 16;
#pragma unroll
            for (int s = 0; s < 5; ++s) {
                int idx = tid + s * 128;
                int t_off = idx / 40, rem = idx % 40;
                int b_off = rem / 10, k = rem % 10;
                stage[s] = g_logits[((size_t)(tb + t_off) * 64 + bbase + b_off) * 10 + k];
            }
        }

        const int tstart = (cchunk == 0) ? 1 : 0;
#pragma unroll 4
        for (int ti = tstart; ti < 16; ++ti) {
            const int t = cchunk * 16 + ti;
            if (lane < 10) sCur[w][lane] = cur;
            __syncwarp();
            float best = sCur[w][0] + trc[0];
            int bi = 0;
#pragma unroll
            for (int i = 1; i < 10; ++i) {
                float v = sCur[w][i] + trc[i];
                if (v > best) { best = v; bi = i; }
            }
            __syncwarp();
            if (lane < 10) {
                cur = sLT[buf][ti][w][lane] + best;
                bp[w][t][lane] = (unsigned char)bi;
            }
        }

        if (cchunk < 31) {
            __syncthreads();
#pragma unroll
            for (int s = 0; s < 5; ++s) {
                int idx = tid + s * 128;
                int t_off = idx / 40, rem = idx % 40;
                int b_off = rem / 10, k = rem % 10;
                sLT[buf ^ 1][t_off][b_off][k] = stage[s];
            }
            __syncthreads();
        }
    }

    if (lane < 10) sCur[w][lane] = cur;
    __syncwarp();
    if (lane == 0) {
        float best = sCur[w][0]; int last = 0;
#pragma unroll
        for (int i = 1; i < 10; ++i)
            if (sCur[w][i] > best) { best = sCur[w][i]; last = i; }
        out[b] = best;
        float* po = out + 64 + (size_t)b * 512;
        int tag = last;
        po[511] = (float)tag;
        for (int t = 511; t >= 1; --t) {
            tag = bp[w][t][tag];
            po[t - 1] = (float)tag;
        }
    }
}

// ---------------------------------------------------------------------------
extern "C" void kernel_launch(void* const* d_in, const int* in_sizes, int n_in,
                              void* d_out, int out_size) {
    const int*   sent  = (const int*)  d_in[0];
    const float* emb   = (const float*)d_in[2];
    const float* Wih_f = (const float*)d_in[3];
    const float* Whh_f = (const float*)d_in[4];
    const float* b_f   = (const float*)d_in[5];
    const float* Wih_b = (const float*)d_in[6];
    const float* Whh_b = (const float*)d_in[7];
    const float* b_b   = (const float*)d_in[8];
    const float* W_out = (const float*)d_in[9];
    const float* b_out = (const float*)d_in[10];
    const float* trans = (const float*)d_in[11];
    float* out = (float*)d_out;

    // launches: 1 init, 2 pregemm, 3 dummy, 4 lstm_rec (ncu slot), 5 logits, 6 viterbi
    init_kernel<<<1, 512>>>();
    pregemm_kernel<<<dim3(8, 256, 2), 256>>>(sent, emb, Wih_f, b_f, Wih_b, b_b);
    dummy_kernel<<<1, 32>>>();
    lstm_rec_kernel<<<128, 256>>>(Whh_f, Whh_b);
    logits_kernel<<<512, 640>>>(W_out, b_out);
    viterbi_kernel<<<16, 128>>>(trans, out);
}

// round 13
// speedup vs baseline: 1.2697x; 1.2697x over previous
#include <cuda_runtime.h>
#include <cuda_bf16.h>
#include <math.h>

// Problem constants
#define BB   64
#define TT   512
#define EE   256
#define HH   256
#define G4   1024
#define KK   10

// -------- device scratch ----------------------------------------------------
__device__ float g_pre[2u * 32768u * 1024u];          // [dir][t*64+b][4H]
__device__ float g_h[2u * 512u * 64u * 256u];         // [dir][t][b][h]
__device__ float g_logits[512u * 64u * 10u];          // [t][b][k]
__device__ unsigned g_bar;

__global__ void init_kernel() { g_bar = 0u; }
__global__ void dummy_kernel() {}

// ---------------------------------------------------------------------------
// Kernel A: fused embedding-gather + GEMM (byte-identical to the 902us config)
// ---------------------------------------------------------------------------
__global__ void __launch_bounds__(256)
pregemm_kernel(const int* __restrict__ sent,
               const float* __restrict__ emb,
               const float* __restrict__ Wih_f,
               const float* __restrict__ b_f,
               const float* __restrict__ Wih_b,
               const float* __restrict__ b_b) {
    const int dir = blockIdx.z;
    const int n0  = blockIdx.x * 128;
    const int m0  = blockIdx.y * 128;
    const float* Wih  = dir ? Wih_b : Wih_f;
    const float* bias = dir ? b_b  : b_f;

    __shared__ float As[2][16][128];
    __shared__ float Bs[2][16][128];
    __shared__ int   toks[128];

    const int tid = threadIdx.x;
    if (tid < 128) {
        int m = m0 + tid;
        toks[tid] = sent[(m & 63) * TT + (m >> 6)];
    }
    __syncthreads();

    const int mA   = tid & 127;
    const int half = tid >> 7;
    const int ty   = tid >> 4;
    const int tx   = tid & 15;

    const float4* emb4 = (const float4*)emb;
    const float4* w4   = (const float4*)Wih;

    const size_t arow = (size_t)toks[mA] * 64;
    const size_t brow = (size_t)(n0 + mA) * 64;

    float acc[8][8];
#pragma unroll
    for (int i = 0; i < 8; ++i)
#pragma unroll
        for (int j = 0; j < 8; ++j) acc[i][j] = 0.f;

    float4 a0g = emb4[arow + half * 2 + 0];
    float4 a1g = emb4[arow + half * 2 + 1];
    float4 b0g = w4  [brow + half * 2 + 0];
    float4 b1g = w4  [brow + half * 2 + 1];

    int buf = 0;
    {
        const int kb = half * 8;
        As[0][kb+0][mA]=a0g.x; As[0][kb+1][mA]=a0g.y; As[0][kb+2][mA]=a0g.z; As[0][kb+3][mA]=a0g.w;
        As[0][kb+4][mA]=a1g.x; As[0][kb+5][mA]=a1g.y; As[0][kb+6][mA]=a1g.z; As[0][kb+7][mA]=a1g.w;
        Bs[0][kb+0][mA]=b0g.x; Bs[0][kb+1][mA]=b0g.y; Bs[0][kb+2][mA]=b0g.z; Bs[0][kb+3][mA]=b0g.w;
        Bs[0][kb+4][mA]=b1g.x; Bs[0][kb+5][mA]=b1g.y; Bs[0][kb+6][mA]=b1g.z; Bs[0][kb+7][mA]=b1g.w;
    }
    __syncthreads();

    for (int kc = 0; kc < 16; ++kc) {
        if (kc < 15) {
            const size_t kq = (size_t)(kc + 1) * 4 + half * 2;
            a0g = emb4[arow + kq];  a1g = emb4[arow + kq + 1];
            b0g = w4  [brow + kq];  b1g = w4  [brow + kq + 1];
        }
#pragma unroll
        for (int kk = 0; kk < 16; ++kk) {
            float4 aA = *(const float4*)&As[buf][kk][ty * 8];
            float4 aB = *(const float4*)&As[buf][kk][ty * 8 + 4];
            float4 bA = *(const float4*)&Bs[buf][kk][tx * 8];
            float4 bB = *(const float4*)&Bs[buf][kk][tx * 8 + 4];
            float av[8] = {aA.x, aA.y, aA.z, aA.w, aB.x, aB.y, aB.z, aB.w};
            float bv[8] = {bA.x, bA.y, bA.z, bA.w, bB.x, bB.y, bB.z, bB.w};
#pragma unroll
            for (int i = 0; i < 8; ++i)
#pragma unroll
                for (int j = 0; j < 8; ++j)
                    acc[i][j] += av[i] * bv[j];
        }
        if (kc < 15) {
            const int nb = buf ^ 1;
            const int kb = half * 8;
            As[nb][kb+0][mA]=a0g.x; As[nb][kb+1][mA]=a0g.y; As[nb][kb+2][mA]=a0g.z; As[nb][kb+3][mA]=a0g.w;
            As[nb][kb+4][mA]=a1g.x; As[nb][kb+5][mA]=a1g.y; As[nb][kb+6][mA]=a1g.z; As[nb][kb+7][mA]=a1g.w;
            Bs[nb][kb+0][mA]=b0g.x; Bs[nb][kb+1][mA]=b0g.y; Bs[nb][kb+2][mA]=b0g.z; Bs[nb][kb+3][mA]=b0g.w;
            Bs[nb][kb+4][mA]=b1g.x; Bs[nb][kb+5][mA]=b1g.y; Bs[nb][kb+6][mA]=b1g.z; Bs[nb][kb+7][mA]=b1g.w;
            __syncthreads();
            buf = nb;
        }
    }

    float4 bv0 = ((const float4*)bias)[(n0 >> 2) + tx * 2];
    float4 bv1 = ((const float4*)bias)[(n0 >> 2) + tx * 2 + 1];
    float4* out4 = (float4*)g_pre;
#pragma unroll
    for (int i = 0; i < 8; ++i) {
        const int m = m0 + ty * 8 + i;
        const size_t row = (size_t)dir * 32768 + m;
        float4 o0, o1;
        o0.x = acc[i][0] + bv0.x; o0.y = acc[i][1] + bv0.y;
        o0.z = acc[i][2] + bv0.z; o0.w = acc[i][3] + bv0.w;
        o1.x = acc[i][4] + bv1.x; o1.y = acc[i][5] + bv1.y;
        o1.z = acc[i][6] + bv1.z; o1.w = acc[i][7] + bv1.w;
        out4[row * 256 + (n0 >> 2) + tx * 2]     = o0;
        out4[row * 256 + (n0 >> 2) + tx * 2 + 1] = o1;
    }
}

// ---------------------------------------------------------------------------
// Kernel B: recurrence. 128 blocks x 512 threads, register weights (64 regs),
// 16 k-slices/unit, bank-conflict-free sHT[k4][b] (pitch 9 float4),
// reduce-scatter shuffle (60 SHFL vs 128), R11 global-counter barrier.
// thread map: u = tid>>4 (32 units), kq = tid&15 (k-slice).
// ---------------------------------------------------------------------------
#define SHT_P 9   // float4 pitch per k4 row (8 batches + 1 pad)

__device__ __forceinline__ float fsigm(float x) {
    return __fdividef(1.f, 1.f + __expf(-x));
}
__device__ __forceinline__ float ftanh(float x) {
    float e = __expf(-2.f * fabsf(x));
    float r = __fdividef(1.f - e, 1.f + e);
    return copysignf(r, x);
}

__global__ void __launch_bounds__(512, 1)
lstm_rec_kernel(const float* __restrict__ Whh_f,
                const float* __restrict__ Whh_b) {
    const int bid = blockIdx.x;
    const int dir = bid >> 6;
    const int ug  = (bid >> 3) & 7;     // unit group (32 units)
    const int bg  = bid & 7;            // batch group (8 batches)
    const int tid = threadIdx.x;        // 512
    const int u   = tid >> 4;           // 0..31 local unit
    const int kq  = tid & 15;           // k-slice
    const int hu  = ug * 32 + u;
    const int bglob = bg * 8 + (kq & 7);

    const float* Whh = dir ? Whh_b : Whh_f;

    __shared__ __align__(16) float4 sHT[64 * SHT_P];   // [k4][b] pitch 9

    // weights in registers: w[g][j] covers float4 k-index kq + j*16
    const float4* whh4 = (const float4*)Whh;
    float4 w[4][4];
#pragma unroll
    for (int g = 0; g < 4; ++g)
#pragma unroll
        for (int j = 0; j < 4; ++j)
            w[g][j] = whh4[((size_t)(g * 256 + hu)) * 64 + kq + j * 16];

    const float4* gh4 = (const float4*)g_h;

    // g_pre prefetch (epilogue lanes only: kq<8)
    const int t0 = dir ? 511 : 0;
    float4 pr = make_float4(0.f, 0.f, 0.f, 0.f);
    if (kq < 8) {
        size_t pb = ((size_t)dir * 32768 + (size_t)t0 * 64 + bglob) * 1024 + hu;
        pr.x = __ldcg(&g_pre[pb]);
        pr.y = __ldcg(&g_pre[pb + 256]);
        pr.z = __ldcg(&g_pre[pb + 512]);
        pr.w = __ldcg(&g_pre[pb + 768]);
    }

    float c = 0.f;
    const int bit2 = (kq >> 2) & 1;
    const int bit1 = (kq >> 1) & 1;
    const int bit0 = kq & 1;

    for (int it = 0; it < 512; ++it) {
        const int t = dir ? (511 - it) : it;

        // ---- stage h(prev): 1 float4 per thread, conflict-free banks ----
        {
            int b_ = tid >> 6, q = tid & 63;
            if (it == 0) {
                sHT[q * SHT_P + b_] = make_float4(0.f, 0.f, 0.f, 0.f);
            } else {
                const int tp = dir ? (t + 1) : (t - 1);
                size_t base = (((size_t)(dir * 512 + tp)) * 64 + bg * 8) * 64;
                sHT[q * SHT_P + b_] = __ldcg(&gh4[base + b_ * 64 + q]);
            }
        }
        __syncthreads();

        // prefetch next step's g_pre (epilogue lanes)
        float4 prn = pr;
        if (it < 511 && kq < 8) {
            const int tn = dir ? (t - 1) : (t + 1);
            size_t pbn = ((size_t)dir * 32768 + (size_t)tn * 64 + bglob) * 1024 + hu;
            prn.x = __ldcg(&g_pre[pbn]);
            prn.y = __ldcg(&g_pre[pbn + 256]);
            prn.z = __ldcg(&g_pre[pbn + 512]);
            prn.w = __ldcg(&g_pre[pbn + 768]);
        }

        // ---- register GEMV: acc[g][b] over this thread's 16-float k-slice --
        float acc[4][8];
#pragma unroll
        for (int g = 0; g < 4; ++g)
#pragma unroll
            for (int b = 0; b < 8; ++b) acc[g][b] = 0.f;

#pragma unroll
        for (int j = 0; j < 4; ++j) {
            const float4* row = &sHT[(kq + j * 16) * SHT_P];
#pragma unroll
            for (int b = 0; b < 8; ++b) {
                float4 h4 = row[b];
#pragma unroll
                for (int g = 0; g < 4; ++g) {
                    acc[g][b] = fmaf(w[g][j].x, h4.x,
                                fmaf(w[g][j].y, h4.y,
                                fmaf(w[g][j].z, h4.z,
                                fmaf(w[g][j].w, h4.w, acc[g][b]))));
                }
            }
        }

        // ---- reduce-scatter over 16 k-slices ----
        // round xor8: full combine (lanes kq, kq+8 hold identical index sets)
#pragma unroll
        for (int g = 0; g < 4; ++g)
#pragma unroll
            for (int b = 0; b < 8; ++b)
                acc[g][b] += __shfl_xor_sync(0xFFFFFFFFu, acc[g][b], 8);

        // round xor4: keep b-half with bit2(b) == bit2(kq)
        float r4[4][4];
#pragma unroll
        for (int g = 0; g < 4; ++g)
#pragma unroll
            for (int i = 0; i < 4; ++i) {
                float a0 = acc[g][i], a1 = acc[g][4 + i];
                float mine = bit2 ? a1 : a0;
                float oth  = bit2 ? a0 : a1;
                r4[g][i] = mine + __shfl_xor_sync(0xFFFFFFFFu, oth, 4);
            }
        // round xor2
        float r2[4][2];
#pragma unroll
        for (int g = 0; g < 4; ++g)
#pragma unroll
            for (int i = 0; i < 2; ++i) {
                float a0 = r4[g][i], a1 = r4[g][2 + i];
                float mine = bit1 ? a1 : a0;
                float oth  = bit1 ? a0 : a1;
                r2[g][i] = mine + __shfl_xor_sync(0xFFFFFFFFu, oth, 2);
            }
        // round xor1
        float s[4];
#pragma unroll
        for (int g = 0; g < 4; ++g) {
            float a0 = r2[g][0], a1 = r2[g][1];
            float mine = bit0 ? a1 : a0;
            float oth  = bit0 ? a0 : a1;
            s[g] = mine + __shfl_xor_sync(0xFFFFFFFFu, oth, 1);
        }
        // lane kq now holds gate sums for batch (kq & 7)

        if (kq < 8) {
            float gi = s[0] + pr.x;
            float gf = s[1] + pr.y;
            float gg = s[2] + pr.z;
            float go = s[3] + pr.w;

            float iv = fsigm(gi), fv = fsigm(gf), gv = ftanh(gg), ov = fsigm(go);
            c = fv * c + iv * gv;
            float hval = ov * ftanh(c);

            g_h[(((size_t)(dir * 512 + t)) * 64 + bglob) * 256 + hu] = hval;
        }

        __syncthreads();   // sHT reads done before next-step overwrite

        if (it < 511) {
            if (tid == 0) {
                __threadfence();
                atomicAdd(&g_bar, 1u);
                unsigned target = 128u * (unsigned)(it + 1);
                volatile unsigned* vb = &g_bar;
                while (*vb < target) { }
            }
            __syncthreads();
            __threadfence();
        }
        pr = prn;
    }
}

// ---------------------------------------------------------------------------
// Kernel C: logits (unchanged)
// ---------------------------------------------------------------------------
__global__ void logits_kernel(const float* __restrict__ Wout,
                              const float* __restrict__ bout) {
    const int t = blockIdx.x;
    __shared__ float sWo[10 * 512];
    __shared__ float sCH[64 * 65];
    __shared__ float sBo[10];

    const int tid = threadIdx.x;      // 640
    for (int idx = tid; idx < 5120; idx += 640) sWo[idx] = Wout[idx];
    if (tid < 10) sBo[tid] = bout[tid];

    const int n = tid / 64, bb = tid & 63;
    float acc = 0.f;
    const float4* gh4 = (const float4*)g_h;

    for (int ch = 0; ch < 8; ++ch) {
        __syncthreads();
        for (int idx = tid; idx < 1024; idx += 640) {
            int b_ = idx >> 4, q = idx & 15;
            int d = ch >> 2;
            int hid4 = (ch & 3) * 16 + q;
            float4 v = gh4[(((size_t)d * 512 + t) * 64 + b_) * 64 + hid4];
            float* dst = &sCH[(q * 4) * 65 + b_];
            dst[0]   = v.x;  dst[65]  = v.y;
            dst[130] = v.z;  dst[195] = v.w;
        }
        __syncthreads();
#pragma unroll 8
        for (int r = 0; r < 64; ++r)
            acc += sWo[n * 512 + ch * 64 + r] * sCH[r * 65 + bb];
    }
    g_logits[((size_t)t * 64 + bb) * 10 + n] = acc + sBo[n];
}

// ---------------------------------------------------------------------------
// Kernel D: Viterbi (unchanged, 63us)
// ---------------------------------------------------------------------------
__global__ void viterbi_kernel(const float* __restrict__ trans,
                               float* __restrict__ out) {
    const int tid  = threadIdx.x;
    const int w    = tid >> 5;
    const int lane = tid & 31;
    const int b    = blockIdx.x * 4 + w;

    __shared__ float         sLT[2][16][4][10];
    __shared__ float         sCur[4][32];
    __shared__ unsigned char bp[4][512][10];
    __shared__ float         tr[100];

    for (int i = tid; i < 100; i += 128) tr[i] = trans[i];

    const int bbase = blockIdx.x * 4;
    float stage[5];
#pragma unroll
    for (int s = 0; s < 5; ++s) {
        int idx = tid + s * 128;
        int t_off = idx / 40, rem = idx % 40;
        int b_off = rem / 10, k = rem % 10;
        stage[s] = g_logits[((size_t)(0 + t_off) * 64 + bbase + b_off) * 10 + k];
    }
#pragma unroll
    for (int s = 0; s < 5; ++s) {
        int idx = tid + s * 128;
        int t_off = idx / 40, rem = idx % 40;
        int b_off = rem / 10, k = rem % 10;
        sLT[0][t_off][b_off][k] = stage[s];
    }
    __syncthreads();

    float trc[10];
#pragma unroll
    for (int i = 0; i < 10; ++i) trc[i] = (lane < 10) ? tr[i * 10 + lane] : 0.f;

    float cur = (lane < 10) ? sLT[0][0][w][lane] : -1e30f;

    for (int cchunk = 0; cchunk < 32; ++cchunk) {
        const int buf = cchunk & 1;
        if (cchunk < 31) {
            const int tb = (cchunk + 1) * 16;
#pragma unroll
            for (int s = 0; s < 5; ++s) {
                int idx = tid + s * 128;
                int t_off = idx / 40, rem = idx % 40;
                int b_off = rem / 10, k = rem % 10;
                stage[s] = g_logits[((size_t)(tb + t_off) * 64 + bbase + b_off) * 10 + k];
            }
        }

        const int tstart = (cchunk == 0) ? 1 : 0;
#pragma unroll 4
        for (int ti = tstart; ti < 16; ++ti) {
            const int t = cchunk * 16 + ti;
            if (lane < 10) sCur[w][lane] = cur;
            __syncwarp();
            float best = sCur[w][0] + trc[0];
            int bi = 0;
#pragma unroll
            for (int i = 1; i < 10; ++i) {
                float v = sCur[w][i] + trc[i];
                if (v > best) { best = v; bi = i; }
            }
            __syncwarp();
            if (lane < 10) {
                cur = sLT[buf][ti][w][lane] + best;
                bp[w][t][lane] = (unsigned char)bi;
            }
        }

        if (cchunk < 31) {
            __syncthreads();
#pragma unroll
            for (int s = 0; s < 5; ++s) {
                int idx = tid + s * 128;
                int t_off = idx / 40, rem = idx % 40;
                int b_off = rem / 10, k = rem % 10;
                sLT[buf ^ 1][t_off][b_off][k] = stage[s];
            }
            __syncthreads();
        }
    }

    if (lane < 10) sCur[w][lane] = cur;
    __syncwarp();
    if (lane == 0) {
        float best = sCur[w][0]; int last = 0;
#pragma unroll
        for (int i = 1; i < 10; ++i)
            if (sCur[w][i] > best) { best = sCur[w][i]; last = i; }
        out[b] = best;
        float* po = out + 64 + (size_t)b * 512;
        int tag = last;
        po[511] = (float)tag;
        for (int t = 511; t >= 1; --t) {
            tag = bp[w][t][tag];
            po[t - 1] = (float)tag;
        }
    }
}

// ---------------------------------------------------------------------------
extern "C" void kernel_launch(void* const* d_in, const int* in_sizes, int n_in,
                              void* d_out, int out_size) {
    const int*   sent  = (const int*)  d_in[0];
    const float* emb   = (const float*)d_in[2];
    const float* Wih_f = (const float*)d_in[3];
    const float* Whh_f = (const float*)d_in[4];
    const float* b_f   = (const float*)d_in[5];
    const float* Wih_b = (const float*)d_in[6];
    const float* Whh_b = (const float*)d_in[7];
    const float* b_b   = (const float*)d_in[8];
    const float* W_out = (const float*)d_in[9];
    const float* b_out = (const float*)d_in[10];
    const float* trans = (const float*)d_in[11];
    float* out = (float*)d_out;

    // launches: 1 init, 2 pregemm, 3 dummy, 4 lstm_rec (ncu slot), 5 logits, 6 viterbi
    init_kernel<<<1, 1>>>();
    pregemm_kernel<<<dim3(8, 256, 2), 256>>>(sent, emb, Wih_f, b_f, Wih_b, b_b);
    dummy_kernel<<<1, 32>>>();
    lstm_rec_kernel<<<128, 512>>>(Whh_f, Whh_b);
    logits_kernel<<<512, 640>>>(W_out, b_out);
    viterbi_kernel<<<16, 128>>>(trans, out);
}

// round 14
// speedup vs baseline: 1.2840x; 1.0113x over previous
#include <cuda_runtime.h>
#include <cuda_bf16.h>
#include <math.h>

// Problem constants
#define BB   64
#define TT   512
#define EE   256
#define HH   256
#define G4   1024
#define KK   10

// -------- device scratch ----------------------------------------------------
__device__ float g_pre[2u * 32768u * 1024u];          // [dir][t*64+b][4H]
__device__ float g_h[2u * 512u * 64u * 256u];         // [dir][t][b][h]
__device__ float g_logits[512u * 64u * 10u];          // [t][b][k]
__device__ unsigned g_barg[16 * 32];                  // 16 group counters, 128B apart

__global__ void init_kernel() {
    int i = threadIdx.x;
    if (i < 16 * 32) g_barg[i] = 0u;
}
__global__ void dummy_kernel() {}

// ---------------------------------------------------------------------------
// Kernel A: fused embedding-gather + GEMM (byte-identical to the 902us config)
// ---------------------------------------------------------------------------
__global__ void __launch_bounds__(256)
pregemm_kernel(const int* __restrict__ sent,
               const float* __restrict__ emb,
               const float* __restrict__ Wih_f,
               const float* __restrict__ b_f,
               const float* __restrict__ Wih_b,
               const float* __restrict__ b_b) {
    const int dir = blockIdx.z;
    const int n0  = blockIdx.x * 128;
    const int m0  = blockIdx.y * 128;
    const float* Wih  = dir ? Wih_b : Wih_f;
    const float* bias = dir ? b_b  : b_f;

    __shared__ float As[2][16][128];
    __shared__ float Bs[2][16][128];
    __shared__ int   toks[128];

    const int tid = threadIdx.x;
    if (tid < 128) {
        int m = m0 + tid;
        toks[tid] = sent[(m & 63) * TT + (m >> 6)];
    }
    __syncthreads();

    const int mA   = tid & 127;
    const int half = tid >> 7;
    const int ty   = tid >> 4;
    const int tx   = tid & 15;

    const float4* emb4 = (const float4*)emb;
    const float4* w4   = (const float4*)Wih;

    const size_t arow = (size_t)toks[mA] * 64;
    const size_t brow = (size_t)(n0 + mA) * 64;

    float acc[8][8];
#pragma unroll
    for (int i = 0; i < 8; ++i)
#pragma unroll
        for (int j = 0; j < 8; ++j) acc[i][j] = 0.f;

    float4 a0g = emb4[arow + half * 2 + 0];
    float4 a1g = emb4[arow + half * 2 + 1];
    float4 b0g = w4  [brow + half * 2 + 0];
    float4 b1g = w4  [brow + half * 2 + 1];

    int buf = 0;
    {
        const int kb = half * 8;
        As[0][kb+0][mA]=a0g.x; As[0][kb+1][mA]=a0g.y; As[0][kb+2][mA]=a0g.z; As[0][kb+3][mA]=a0g.w;
        As[0][kb+4][mA]=a1g.x; As[0][kb+5][mA]=a1g.y; As[0][kb+6][mA]=a1g.z; As[0][kb+7][mA]=a1g.w;
        Bs[0][kb+0][mA]=b0g.x; Bs[0][kb+1][mA]=b0g.y; Bs[0][kb+2][mA]=b0g.z; Bs[0][kb+3][mA]=b0g.w;
        Bs[0][kb+4][mA]=b1g.x; Bs[0][kb+5][mA]=b1g.y; Bs[0][kb+6][mA]=b1g.z; Bs[0][kb+7][mA]=b1g.w;
    }
    __syncthreads();

    for (int kc = 0; kc < 16; ++kc) {
        if (kc < 15) {
            const size_t kq = (size_t)(kc + 1) * 4 + half * 2;
            a0g = emb4[arow + kq];  a1g = emb4[arow + kq + 1];
            b0g = w4  [brow + kq];  b1g = w4  [brow + kq + 1];
        }
#pragma unroll
        for (int kk = 0; kk < 16; ++kk) {
            float4 aA = *(const float4*)&As[buf][kk][ty * 8];
            float4 aB = *(const float4*)&As[buf][kk][ty * 8 + 4];
            float4 bA = *(const float4*)&Bs[buf][kk][tx * 8];
            float4 bB = *(const float4*)&Bs[buf][kk][tx * 8 + 4];
            float av[8] = {aA.x, aA.y, aA.z, aA.w, aB.x, aB.y, aB.z, aB.w};
            float bv[8] = {bA.x, bA.y, bA.z, bA.w, bB.x, bB.y, bB.z, bB.w};
#pragma unroll
            for (int i = 0; i < 8; ++i)
#pragma unroll
                for (int j = 0; j < 8; ++j)
                    acc[i][j] += av[i] * bv[j];
        }
        if (kc < 15) {
            const int nb = buf ^ 1;
            const int kb = half * 8;
            As[nb][kb+0][mA]=a0g.x; As[nb][kb+1][mA]=a0g.y; As[nb][kb+2][mA]=a0g.z; As[nb][kb+3][mA]=a0g.w;
            As[nb][kb+4][mA]=a1g.x; As[nb][kb+5][mA]=a1g.y; As[nb][kb+6][mA]=a1g.z; As[nb][kb+7][mA]=a1g.w;
            Bs[nb][kb+0][mA]=b0g.x; Bs[nb][kb+1][mA]=b0g.y; Bs[nb][kb+2][mA]=b0g.z; Bs[nb][kb+3][mA]=b0g.w;
            Bs[nb][kb+4][mA]=b1g.x; Bs[nb][kb+5][mA]=b1g.y; Bs[nb][kb+6][mA]=b1g.z; Bs[nb][kb+7][mA]=b1g.w;
            __syncthreads();
            buf = nb;
        }
    }

    float4 bv0 = ((const float4*)bias)[(n0 >> 2) + tx * 2];
    float4 bv1 = ((const float4*)bias)[(n0 >> 2) + tx * 2 + 1];
    float4* out4 = (float4*)g_pre;
#pragma unroll
    for (int i = 0; i < 8; ++i) {
        const int m = m0 + ty * 8 + i;
        const size_t row = (size_t)dir * 32768 + m;
        float4 o0, o1;
        o0.x = acc[i][0] + bv0.x; o0.y = acc[i][1] + bv0.y;
        o0.z = acc[i][2] + bv0.z; o0.w = acc[i][3] + bv0.w;
        o1.x = acc[i][4] + bv1.x; o1.y = acc[i][5] + bv1.y;
        o1.z = acc[i][6] + bv1.z; o1.w = acc[i][7] + bv1.w;
        out4[row * 256 + (n0 >> 2) + tx * 2]     = o0;
        out4[row * 256 + (n0 >> 2) + tx * 2 + 1] = o1;
    }
}

// ---------------------------------------------------------------------------
// Kernel B: recurrence (R13 core, UNCHANGED except the barrier):
// PER-GROUP barrier — group = (dir, bg), 8 blocks, own 128B counter line.
// ---------------------------------------------------------------------------
#define SHT_P 9   // float4 pitch per k4 row (8 batches + 1 pad)

__device__ __forceinline__ float fsigm(float x) {
    return __fdividef(1.f, 1.f + __expf(-x));
}
__device__ __forceinline__ float ftanh(float x) {
    float e = __expf(-2.f * fabsf(x));
    float r = __fdividef(1.f - e, 1.f + e);
    return copysignf(r, x);
}

__global__ void __launch_bounds__(512, 1)
lstm_rec_kernel(const float* __restrict__ Whh_f,
                const float* __restrict__ Whh_b) {
    const int bid = blockIdx.x;
    const int dir = bid >> 6;
    const int ug  = (bid >> 3) & 7;     // unit group (32 units)
    const int bg  = bid & 7;            // batch group (8 batches)
    const int grp = dir * 8 + bg;       // sync group: the 8 blocks (dir,*,bg)
    const int tid = threadIdx.x;        // 512
    const int u   = tid >> 4;           // 0..31 local unit
    const int kq  = tid & 15;           // k-slice
    const int hu  = ug * 32 + u;
    const int bglob = bg * 8 + (kq & 7);

    const float* Whh = dir ? Whh_b : Whh_f;

    __shared__ __align__(16) float4 sHT[64 * SHT_P];   // [k4][b] pitch 9

    // weights in registers: w[g][j] covers float4 k-index kq + j*16
    const float4* whh4 = (const float4*)Whh;
    float4 w[4][4];
#pragma unroll
    for (int g = 0; g < 4; ++g)
#pragma unroll
        for (int j = 0; j < 4; ++j)
            w[g][j] = whh4[((size_t)(g * 256 + hu)) * 64 + kq + j * 16];

    const float4* gh4 = (const float4*)g_h;
    volatile unsigned* bar = &g_barg[grp * 32];

    // g_pre prefetch (epilogue lanes only: kq<8)
    const int t0 = dir ? 511 : 0;
    float4 pr = make_float4(0.f, 0.f, 0.f, 0.f);
    if (kq < 8) {
        size_t pb = ((size_t)dir * 32768 + (size_t)t0 * 64 + bglob) * 1024 + hu;
        pr.x = __ldcg(&g_pre[pb]);
        pr.y = __ldcg(&g_pre[pb + 256]);
        pr.z = __ldcg(&g_pre[pb + 512]);
        pr.w = __ldcg(&g_pre[pb + 768]);
    }

    float c = 0.f;
    const int bit2 = (kq >> 2) & 1;
    const int bit1 = (kq >> 1) & 1;
    const int bit0 = kq & 1;

    for (int it = 0; it < 512; ++it) {
        const int t = dir ? (511 - it) : it;

        // ---- stage h(prev): 1 float4 per thread, conflict-free banks ----
        {
            int b_ = tid >> 6, q = tid & 63;
            if (it == 0) {
                sHT[q * SHT_P + b_] = make_float4(0.f, 0.f, 0.f, 0.f);
            } else {
                const int tp = dir ? (t + 1) : (t - 1);
                size_t base = (((size_t)(dir * 512 + tp)) * 64 + bg * 8) * 64;
                sHT[q * SHT_P + b_] = __ldcg(&gh4[base + b_ * 64 + q]);
            }
        }
        __syncthreads();

        // prefetch next step's g_pre (epilogue lanes)
        float4 prn = pr;
        if (it < 511 && kq < 8) {
            const int tn = dir ? (t - 1) : (t + 1);
            size_t pbn = ((size_t)dir * 32768 + (size_t)tn * 64 + bglob) * 1024 + hu;
            prn.x = __ldcg(&g_pre[pbn]);
            prn.y = __ldcg(&g_pre[pbn + 256]);
            prn.z = __ldcg(&g_pre[pbn + 512]);
            prn.w = __ldcg(&g_pre[pbn + 768]);
        }

        // ---- register GEMV: acc[g][b] over this thread's 16-float k-slice --
        float acc[4][8];
#pragma unroll
        for (int g = 0; g < 4; ++g)
#pragma unroll
            for (int b = 0; b < 8; ++b) acc[g][b] = 0.f;

#pragma unroll
        for (int j = 0; j < 4; ++j) {
            const float4* row = &sHT[(kq + j * 16) * SHT_P];
#pragma unroll
            for (int b = 0; b < 8; ++b) {
                float4 h4 = row[b];
#pragma unroll
                for (int g = 0; g < 4; ++g) {
                    acc[g][b] = fmaf(w[g][j].x, h4.x,
                                fmaf(w[g][j].y, h4.y,
                                fmaf(w[g][j].z, h4.z,
                                fmaf(w[g][j].w, h4.w, acc[g][b]))));
                }
            }
        }

        // ---- reduce-scatter over 16 k-slices ----
#pragma unroll
        for (int g = 0; g < 4; ++g)
#pragma unroll
            for (int b = 0; b < 8; ++b)
                acc[g][b] += __shfl_xor_sync(0xFFFFFFFFu, acc[g][b], 8);

        float r4[4][4];
#pragma unroll
        for (int g = 0; g < 4; ++g)
#pragma unroll
            for (int i = 0; i < 4; ++i) {
                float a0 = acc[g][i], a1 = acc[g][4 + i];
                float mine = bit2 ? a1 : a0;
                float oth  = bit2 ? a0 : a1;
                r4[g][i] = mine + __shfl_xor_sync(0xFFFFFFFFu, oth, 4);
            }
        float r2[4][2];
#pragma unroll
        for (int g = 0; g < 4; ++g)
#pragma unroll
            for (int i = 0; i < 2; ++i) {
                float a0 = r4[g][i], a1 = r4[g][2 + i];
                float mine = bit1 ? a1 : a0;
                float oth  = bit1 ? a0 : a1;
                r2[g][i] = mine + __shfl_xor_sync(0xFFFFFFFFu, oth, 2);
            }
        float s[4];
#pragma unroll
        for (int g = 0; g < 4; ++g) {
            float a0 = r2[g][0], a1 = r2[g][1];
            float mine = bit0 ? a1 : a0;
            float oth  = bit0 ? a0 : a1;
            s[g] = mine + __shfl_xor_sync(0xFFFFFFFFu, oth, 1);
        }

        if (kq < 8) {
            float gi = s[0] + pr.x;
            float gf = s[1] + pr.y;
            float gg = s[2] + pr.z;
            float go = s[3] + pr.w;

            float iv = fsigm(gi), fv = fsigm(gf), gv = ftanh(gg), ov = fsigm(go);
            c = fv * c + iv * gv;
            float hval = ov * ftanh(c);

            g_h[(((size_t)(dir * 512 + t)) * 64 + bglob) * 256 + hu] = hval;
        }

        __syncthreads();   // sHT reads done before next-step overwrite

        if (it < 511) {
            if (tid == 0) {
                __threadfence();
                atomicAdd((unsigned*)bar, 1u);
                unsigned target = 8u * (unsigned)(it + 1);
                while (*bar < target) { }
            }
            __syncthreads();
            __threadfence();
        }
        pr = prn;
    }
}

// ---------------------------------------------------------------------------
// Kernel C: logits (unchanged)
// ---------------------------------------------------------------------------
__global__ void logits_kernel(const float* __restrict__ Wout,
                              const float* __restrict__ bout) {
    const int t = blockIdx.x;
    __shared__ float sWo[10 * 512];
    __shared__ float sCH[64 * 65];
    __shared__ float sBo[10];

    const int tid = threadIdx.x;      // 640
    for (int idx = tid; idx < 5120; idx += 640) sWo[idx] = Wout[idx];
    if (tid < 10) sBo[tid] = bout[tid];

    const int n = tid / 64, bb = tid & 63;
    float acc = 0.f;
    const float4* gh4 = (const float4*)g_h;

    for (int ch = 0; ch < 8; ++ch) {
        __syncthreads();
        for (int idx = tid; idx < 1024; idx += 640) {
            int b_ = idx >> 4, q = idx & 15;
            int d = ch >> 2;
            int hid4 = (ch & 3) * 16 + q;
            float4 v = gh4[(((size_t)d * 512 + t) * 64 + b_) * 64 + hid4];
            float* dst = &sCH[(q * 4) * 65 + b_];
            dst[0]   = v.x;  dst[65]  = v.y;
            dst[130] = v.z;  dst[195] = v.w;
        }
        __syncthreads();
#pragma unroll 8
        for (int r = 0; r < 64; ++r)
            acc += sWo[n * 512 + ch * 64 + r] * sCH[r * 65 + bb];
    }
    g_logits[((size_t)t * 64 + bb) * 10 + n] = acc + sBo[n];
}

// ---------------------------------------------------------------------------
// Kernel D: Viterbi (unchanged, 63us)
// ---------------------------------------------------------------------------
__global__ void viterbi_kernel(const float* __restrict__ trans,
                               float* __restrict__ out) {
    const int tid  = threadIdx.x;
    const int w    = tid >> 5;
    const int lane = tid & 31;
    const int b    = blockIdx.x * 4 + w;

    __shared__ float         sLT[2][16][4][10];
    __shared__ float         sCur[4][32];
    __shared__ unsigned char bp[4][512][10];
    __shared__ float         tr[100];

    for (int i = tid; i < 100; i += 128) tr[i] = trans[i];

    const int bbase = blockIdx.x * 4;
    float stage[5];
#pragma unroll
    for (int s = 0; s < 5; ++s) {
        int idx = tid + s * 128;
        int t_off = idx / 40, rem = idx % 40;
        int b_off = rem / 10, k = rem % 10;
        stage[s] = g_logits[((size_t)(0 + t_off) * 64 + bbase + b_off) * 10 + k];
    }
#pragma unroll
    for (int s = 0; s < 5; ++s) {
        int idx = tid + s * 128;
        int t_off = idx / 40, rem = idx % 40;
        int b_off = rem / 10, k = rem % 10;
        sLT[0][t_off][b_off][k] = stage[s];
    }
    __syncthreads();

    float trc[10];
#pragma unroll
    for (int i = 0; i < 10; ++i) trc[i] = (lane < 10) ? tr[i * 10 + lane] : 0.f;

    float cur = (lane < 10) ? sLT[0][0][w][lane] : -1e30f;

    for (int cchunk = 0; cchunk < 32; ++cchunk) {
        const int buf = cchunk & 1;
        if (cchunk < 31) {
            const int tb = (cchunk + 1) * 16;
#pragma unroll
            for (int s = 0; s < 5; ++s) {
                int idx = tid + s * 128;
                int t_off = idx / 40, rem = idx % 40;
                int b_off = rem / 10, k = rem % 10;
                stage[s] = g_logits[((size_t)(tb + t_off) * 64 + bbase + b_off) * 10 + k];
            }
        }

        const int tstart = (cchunk == 0) ? 1 : 0;
#pragma unroll 4
        for (int ti = tstart; ti < 16; ++ti) {
            const int t = cchunk * 16 + ti;
            if (lane < 10) sCur[w][lane] = cur;
            __syncwarp();
            float best = sCur[w][0] + trc[0];
            int bi = 0;
#pragma unroll
            for (int i = 1; i < 10; ++i) {
                float v = sCur[w][i] + trc[i];
                if (v > best) { best = v; bi = i; }
            }
            __syncwarp();
            if (lane < 10) {
                cur = sLT[buf][ti][w][lane] + best;
                bp[w][t][lane] = (unsigned char)bi;
            }
        }

        if (cchunk < 31) {
            __syncthreads();
#pragma unroll
            for (int s = 0; s < 5; ++s) {
                int idx = tid + s * 128;
                int t_off = idx / 40, rem = idx % 40;
                int b_off = rem / 10, k = rem % 10;
                sLT[buf ^ 1][t_off][b_off][k] = stage[s];
            }
            __syncthreads();
        }
    }

    if (lane < 10) sCur[w][lane] = cur;
    __syncwarp();
    if (lane == 0) {
        float best = sCur[w][0]; int last = 0;
#pragma unroll
        for (int i = 1; i < 10; ++i)
            if (sCur[w][i] > best) { best = sCur[w][i]; last = i; }
        out[b] = best;
        float* po = out + 64 + (size_t)b * 512;
        int tag = last;
        po[511] = (float)tag;
        for (int t = 511; t >= 1; --t) {
            tag = bp[w][t][tag];
            po[t - 1] = (float)tag;
        }
    }
}

// ---------------------------------------------------------------------------
extern "C" void kernel_launch(void* const* d_in, const int* in_sizes, int n_in,
                              void* d_out, int out_size) {
    const int*   sent  = (const int*)  d_in[0];
    const float* emb   = (const float*)d_in[2];
    const float* Wih_f = (const float*)d_in[3];
    const float* Whh_f = (const float*)d_in[4];
    const float* b_f   = (const float*)d_in[5];
    const float* Wih_b = (const float*)d_in[6];
    const float* Whh_b = (const float*)d_in[7];
    const float* b_b   = (const float*)d_in[8];
    const float* W_out = (const float*)d_in[9];
    const float* b_out = (const float*)d_in[10];
    const float* trans = (const float*)d_in[11];
    float* out = (float*)d_out;

    // launches: 1 init, 2 pregemm, 3 dummy, 4 lstm_rec (ncu slot), 5 logits, 6 viterbi
    init_kernel<<<1, 512>>>();
    pregemm_kernel<<<dim3(8, 256, 2), 256>>>(sent, emb, Wih_f, b_f, Wih_b, b_b);
    dummy_kernel<<<1, 32>>>();
    lstm_rec_kernel<<<128, 512>>>(Whh_f, Whh_b);
    logits_kernel<<<512, 640>>>(W_out, b_out);
    viterbi_kernel<<<16, 128>>>(trans, out);
}

// round 16
// speedup vs baseline: 1.3334x; 1.0385x over previous
#include <cuda_runtime.h>
#include <cuda_bf16.h>
#include <math.h>

// Problem constants
#define BB   64
#define TT   512
#define EE   256
#define HH   256
#define G4   1024
#define KK   10

// tcgen05 is only legal in the sm_103a ('all-features') compilation pass.
#if defined(__CUDA_ARCH__) && defined(__CUDA_ARCH_FEAT_SM103_ALL)
#define PG_TC 1
#else
#define PG_TC 0
#endif

// -------- device scratch ----------------------------------------------------
__device__ float g_pre[2u * 32768u * 1024u];          // [dir][t*64+b][4H]
__device__ float g_h[2u * 512u * 64u * 256u];         // [dir][t][b][h]
__device__ float g_logits[512u * 64u * 10u];          // [t][b][k]
__device__ unsigned g_barg[16 * 32];                  // 16 group counters, 128B apart

__global__ void init_kernel() {
    int i = threadIdx.x;
    if (i < 16 * 32) g_barg[i] = 0u;
}
__global__ void dummy_kernel() {}

// ======================= tcgen05 / PTX helpers ==============================
__device__ __forceinline__ unsigned smem_u32(const void* p) {
    unsigned a;
    asm("{ .reg .u64 t; cvta.to.shared.u64 t, %1; cvt.u32.u64 %0, t; }"
        : "=r"(a) : "l"(p));
    return a;
}
#define SW128(off) ((off) ^ (((off) >> 3) & 0x70))

#if PG_TC
__device__ __forceinline__ unsigned elect_one() {
    unsigned pred;
    asm volatile("{\n\t.reg .pred p;\n\t"
                 "elect.sync _|p, 0xFFFFFFFF;\n\t"
                 "selp.b32 %0, 1, 0, p;\n\t}" : "=r"(pred));
    return pred;
}
static __device__ __forceinline__ unsigned long long make_desc(unsigned addr) {
    // SW128, Blackwell v1, SBO=64, LBO=1
    const unsigned long long base =
        (2ull << 61) | (1ull << 46) | (64ull << 32) | (1ull << 16);
    return base | ((unsigned long long)(addr >> 4) & 0x3FFFull);
}
__device__ __forceinline__ void tc_alloc(unsigned ctrl_addr, unsigned ncols) {
    asm volatile("tcgen05.alloc.cta_group::1.sync.aligned.shared::cta.b32 [%0], %1;"
                 :: "r"(ctrl_addr), "r"(ncols) : "memory");
}
__device__ __forceinline__ void tc_dealloc(unsigned tmem, unsigned ncols) {
    asm volatile("tcgen05.dealloc.cta_group::1.sync.aligned.b32 %0, %1;"
                 :: "r"(tmem), "r"(ncols));
}
__device__ __forceinline__ void mma_f16_ss(unsigned d_tmem,
                                           unsigned long long a_desc,
                                           unsigned long long b_desc,
                                           unsigned idesc, unsigned en) {
    asm volatile(
        "{\n\t.reg .pred p;\n\t"
        "setp.ne.u32 p, %4, 0;\n\t"
        "tcgen05.mma.cta_group::1.kind::f16 [%0], %1, %2, %3, {%5,%5,%5,%5}, p;\n\t}"
        :: "r"(d_tmem), "l"(a_desc), "l"(b_desc), "r"(idesc), "r"(en), "r"(0u)
        : "memory");
}
__device__ __forceinline__ void tc_commit(unsigned mbar) {
    asm volatile(
        "tcgen05.commit.cta_group::1.mbarrier::arrive::one.shared::cluster.b64 [%0];"
        :: "r"(mbar) : "memory");
}
__device__ __forceinline__ void mbar_init1(unsigned mbar) {
    asm volatile("mbarrier.init.shared.b64 [%0], 1;" :: "r"(mbar) : "memory");
}
__device__ __forceinline__ void mbar_inval(unsigned mbar) {
    asm volatile("mbarrier.inval.shared.b64 [%0];" :: "r"(mbar) : "memory");
}
__device__ __forceinline__ void mbar_wait(unsigned mbar, unsigned parity) {
    asm volatile(
        "{\n\t.reg .pred P1;\n\t"
        "WAIT_%=:\n\t"
        "mbarrier.try_wait.parity.acquire.cta.shared::cta.b64 P1, [%0], %1, 0x989680;\n\t"
        "@P1 bra.uni DONE_%=;\n\t"
        "bra.uni WAIT_%=;\n\t"
        "DONE_%=:\n\t}"
        :: "r"(mbar), "r"(parity) : "memory");
}
__device__ __forceinline__ void fence_async_smem() {
    asm volatile("fence.proxy.async.shared::cta;" ::: "memory");
}
__device__ __forceinline__ void tc_fence_after() {
    asm volatile("tcgen05.fence::after_thread_sync;" ::: "memory");
}
__device__ __forceinline__ void tc_fence_before() {
    asm volatile("tcgen05.fence::before_thread_sync;" ::: "memory");
}
__device__ __forceinline__ void tc_wait_ld() {
    asm volatile("tcgen05.wait::ld.sync.aligned;" ::: "memory");
}
#define TC_LD_X32(r, addr) \
    asm volatile( \
        "tcgen05.ld.sync.aligned.32x32b.x32.b32 " \
        "{%0,%1,%2,%3,%4,%5,%6,%7,%8,%9,%10,%11,%12,%13,%14,%15," \
        "%16,%17,%18,%19,%20,%21,%22,%23,%24,%25,%26,%27,%28,%29,%30,%31}, [%32];" \
        : "=r"((r)[0]),"=r"((r)[1]),"=r"((r)[2]),"=r"((r)[3]), \
          "=r"((r)[4]),"=r"((r)[5]),"=r"((r)[6]),"=r"((r)[7]), \
          "=r"((r)[8]),"=r"((r)[9]),"=r"((r)[10]),"=r"((r)[11]), \
          "=r"((r)[12]),"=r"((r)[13]),"=r"((r)[14]),"=r"((r)[15]), \
          "=r"((r)[16]),"=r"((r)[17]),"=r"((r)[18]),"=r"((r)[19]), \
          "=r"((r)[20]),"=r"((r)[21]),"=r"((r)[22]),"=r"((r)[23]), \
          "=r"((r)[24]),"=r"((r)[25]),"=r"((r)[26]),"=r"((r)[27]), \
          "=r"((r)[28]),"=r"((r)[29]),"=r"((r)[30]),"=r"((r)[31]) \
        : "r"(addr))

// idesc: dtype F32, atype/btype BF16, N=128, M=128 (cg1)
#define MMA_IDESC ((1u << 4) | (1u << 7) | (1u << 10) | (16u << 17) | (8u << 24))

// split fp32 -> 3 bf16 limbs (residuals exactly representable)
__device__ __forceinline__ void split3(float x, unsigned short& h,
                                       unsigned short& m, unsigned short& l) {
    __nv_bfloat16 bh = __float2bfloat16(x);
    float hf = __bfloat162float(bh);
    __nv_bfloat16 bm = __float2bfloat16(x - hf);
    float mf = __bfloat162float(bm);
    __nv_bfloat16 bl = __float2bfloat16(x - hf - mf);
    h = *(unsigned short*)&bh;
    m = *(unsigned short*)&bm;
    l = *(unsigned short*)&bl;
}
#endif  // PG_TC

// smem layout (tensor path): A_hi..A_lo, B_hi..B_lo (16KB each) + ctrl
#define TILE_B   16384
#define CTRL_OFF (6 * TILE_B)
#define PG_SMEM  (CTRL_OFF + 128 + 1024)

// ---------------------------------------------------------------------------
// Kernel A: g_pre = emb[sent] @ Wih^T + bias.
//  PG_TC:  tcgen05 bf16 multi-split (8 limb MMAs, fp32-accurate)
//  else:   fp32 register-blocked GEMM (the proven 902us code), smem in dsm
// grid (8 n-tiles, 256 m-tiles, 2 dir), 256 threads, PG_SMEM dynamic smem.
// ---------------------------------------------------------------------------
__global__ void __launch_bounds__(256)
pregemm_kernel(const int* __restrict__ sent,
               const float* __restrict__ emb,
               const float* __restrict__ Wih_f,
               const float* __restrict__ b_f,
               const float* __restrict__ Wih_b,
               const float* __restrict__ b_b) {
    const int dir = blockIdx.z;
    const int n0  = blockIdx.x * 128;
    const int m0  = blockIdx.y * 128;
    const float* Wih  = dir ? Wih_b : Wih_f;
    const float* bias = dir ? b_b  : b_f;

    extern __shared__ char dsm[];
    const int tid = threadIdx.x;

#if PG_TC
    // ======================= TENSOR PATH =======================
    char* base = (char*)(((size_t)dsm + 1023) & ~(size_t)1023);
    const unsigned sb = smem_u32(base);
    char* tA[3] = { base,              base + TILE_B,     base + 2 * TILE_B };
    char* tB[3] = { base + 3 * TILE_B, base + 4 * TILE_B, base + 5 * TILE_B };
    unsigned ctrl = sb + CTRL_OFF;

    const int wid = tid >> 5;
    const int lid = tid & 31;

    __shared__ int toks[128];
    if (tid < 128) {
        int m = m0 + tid;
        toks[tid] = sent[(m & 63) * TT + (m >> 6)];
    }
    if (wid == 0) tc_alloc(ctrl, 128);
    if (tid == 0) mbar_init1(ctrl + 8);
    __syncthreads();
    unsigned tmem;
    asm volatile("ld.shared.b32 %0, [%1];" : "=r"(tmem) : "r"(ctrl));

    const int passA[8] = {0, 0, 1, 1, 0, 2, 1, 2};
    const int passB[8] = {0, 1, 0, 1, 2, 0, 2, 1};

    for (int kc = 0; kc < 4; ++kc) {
        const int k0 = kc * 64;
        if (kc > 0) mbar_wait(ctrl + 8, (unsigned)((kc - 1) & 1));

#pragma unroll
        for (int i = 0; i < 8; ++i) {
            int idx = i * 256 + tid;
            int row = idx >> 4, c4 = idx & 15;
            float4 v = *(const float4*)&emb[(size_t)toks[row] * 256 + k0 + c4 * 4];
            unsigned short h[4], mm[4], l[4];
            split3(v.x, h[0], mm[0], l[0]);
            split3(v.y, h[1], mm[1], l[1]);
            split3(v.z, h[2], mm[2], l[2]);
            split3(v.w, h[3], mm[3], l[3]);
            unsigned off = SW128((unsigned)(row * 128 + c4 * 8));
            *(ushort4*)(tA[0] + off) = make_ushort4(h[0], h[1], h[2], h[3]);
            *(ushort4*)(tA[1] + off) = make_ushort4(mm[0], mm[1], mm[2], mm[3]);
            *(ushort4*)(tA[2] + off) = make_ushort4(l[0], l[1], l[2], l[3]);
        }
#pragma unroll
        for (int i = 0; i < 8; ++i) {
            int idx = i * 256 + tid;
            int row = idx >> 4, c4 = idx & 15;
            float4 v = *(const float4*)&Wih[(size_t)(n0 + row) * 256 + k0 + c4 * 4];
            unsigned short h[4], mm[4], l[4];
            split3(v.x, h[0], mm[0], l[0]);
            split3(v.y, h[1], mm[1], l[1]);
            split3(v.z, h[2], mm[2], l[2]);
            split3(v.w, h[3], mm[3], l[3]);
            unsigned off = SW128((unsigned)(row * 128 + c4 * 8));
            *(ushort4*)(tB[0] + off) = make_ushort4(h[0], h[1], h[2], h[3]);
            *(ushort4*)(tB[1] + off) = make_ushort4(mm[0], mm[1], mm[2], mm[3]);
            *(ushort4*)(tB[2] + off) = make_ushort4(l[0], l[1], l[2], l[3]);
        }
        fence_async_smem();
        __syncthreads();

        if (wid == 0 && elect_one()) {
            unsigned long long dA[3] = {
                make_desc(sb + 0 * TILE_B), make_desc(sb + 1 * TILE_B),
                make_desc(sb + 2 * TILE_B) };
            unsigned long long dB[3] = {
                make_desc(sb + 3 * TILE_B), make_desc(sb + 4 * TILE_B),
                make_desc(sb + 5 * TILE_B) };
#pragma unroll
            for (int p = 0; p < 8; ++p) {
#pragma unroll
                for (int k = 0; k < 4; ++k) {
                    unsigned en = (kc == 0 && p == 0 && k == 0) ? 0u : 1u;
                    mma_f16_ss(tmem, dA[passA[p]] + k * 2,
                               dB[passB[p]] + k * 2, MMA_IDESC, en);
                }
            }
            tc_commit(ctrl + 8);
        }
        __syncthreads();
    }

    mbar_wait(ctrl + 8, 1u);
    tc_fence_after();

    if (wid < 4) {
        const int m = m0 + wid * 32 + lid;
        const size_t rowbase = ((size_t)dir * 32768 + m) * 256 + (n0 >> 2);
        float4* out4 = (float4*)g_pre;
        const float4* bias4 = (const float4*)bias;
#pragma unroll
        for (int cb = 0; cb < 4; ++cb) {
            unsigned d[32];
            TC_LD_X32(d, tmem + cb * 32);
            tc_wait_ld();
#pragma unroll
            for (int q = 0; q < 8; ++q) {
                float4 bv = bias4[(n0 >> 2) + cb * 8 + q];
                float4 o;
                o.x = __uint_as_float(d[q * 4 + 0]) + bv.x;
                o.y = __uint_as_float(d[q * 4 + 1]) + bv.y;
                o.z = __uint_as_float(d[q * 4 + 2]) + bv.z;
                o.w = __uint_as_float(d[q * 4 + 3]) + bv.w;
                out4[rowbase + cb * 8 + q] = o;
            }
        }
        tc_fence_before();
    }
    __syncthreads();
    if (tid == 0) mbar_inval(ctrl + 8);
    __syncthreads();
    if (wid == 0) tc_dealloc(tmem, 128);

#else
    // ======================= FP32 FALLBACK (902us code, smem in dsm) =======
    float* As = (float*)dsm;                     // [2][16][128]
    float* Bs = (float*)(dsm + 16384);           // [2][16][128]
    int*  toks = (int*)(dsm + 32768);            // [128]
#define AS(bf, k, m_) As[(bf) * 2048 + (k) * 128 + (m_)]
#define BS(bf, k, m_) Bs[(bf) * 2048 + (k) * 128 + (m_)]

    if (tid < 128) {
        int m = m0 + tid;
        toks[tid] = sent[(m & 63) * TT + (m >> 6)];
    }
    __syncthreads();

    const int mA   = tid & 127;
    const int half = tid >> 7;
    const int ty   = tid >> 4;
    const int tx   = tid & 15;

    const float4* emb4 = (const float4*)emb;
    const float4* w4   = (const float4*)Wih;

    const size_t arow = (size_t)toks[mA] * 64;
    const size_t brow = (size_t)(n0 + mA) * 64;

    float acc[8][8];
#pragma unroll
    for (int i = 0; i < 8; ++i)
#pragma unroll
        for (int j = 0; j < 8; ++j) acc[i][j] = 0.f;

    float4 a0g = emb4[arow + half * 2 + 0];
    float4 a1g = emb4[arow + half * 2 + 1];
    float4 b0g = w4  [brow + half * 2 + 0];
    float4 b1g = w4  [brow + half * 2 + 1];

    int buf = 0;
    {
        const int kb = half * 8;
        AS(0,kb+0,mA)=a0g.x; AS(0,kb+1,mA)=a0g.y; AS(0,kb+2,mA)=a0g.z; AS(0,kb+3,mA)=a0g.w;
        AS(0,kb+4,mA)=a1g.x; AS(0,kb+5,mA)=a1g.y; AS(0,kb+6,mA)=a1g.z; AS(0,kb+7,mA)=a1g.w;
        BS(0,kb+0,mA)=b0g.x; BS(0,kb+1,mA)=b0g.y; BS(0,kb+2,mA)=b0g.z; BS(0,kb+3,mA)=b0g.w;
        BS(0,kb+4,mA)=b1g.x; BS(0,kb+5,mA)=b1g.y; BS(0,kb+6,mA)=b1g.z; BS(0,kb+7,mA)=b1g.w;
    }
    __syncthreads();

    for (int kc = 0; kc < 16; ++kc) {
        if (kc < 15) {
            const size_t kq = (size_t)(kc + 1) * 4 + half * 2;
            a0g = emb4[arow + kq];  a1g = emb4[arow + kq + 1];
            b0g = w4  [brow + kq];  b1g = w4  [brow + kq + 1];
        }
#pragma unroll
        for (int kk = 0; kk < 16; ++kk) {
            float4 aA = *(const float4*)&AS(buf, kk, ty * 8);
            float4 aB = *(const float4*)&AS(buf, kk, ty * 8 + 4);
            float4 bA = *(const float4*)&BS(buf, kk, tx * 8);
            float4 bB = *(const float4*)&BS(buf, kk, tx * 8 + 4);
            float av[8] = {aA.x, aA.y, aA.z, aA.w, aB.x, aB.y, aB.z, aB.w};
            float bv[8] = {bA.x, bA.y, bA.z, bA.w, bB.x, bB.y, bB.z, bB.w};
#pragma unroll
            for (int i = 0; i < 8; ++i)
#pragma unroll
                for (int j = 0; j < 8; ++j)
                    acc[i][j] += av[i] * bv[j];
        }
        if (kc < 15) {
            const int nb = buf ^ 1;
            const int kb = half * 8;
            AS(nb,kb+0,mA)=a0g.x; AS(nb,kb+1,mA)=a0g.y; AS(nb,kb+2,mA)=a0g.z; AS(nb,kb+3,mA)=a0g.w;
            AS(nb,kb+4,mA)=a1g.x; AS(nb,kb+5,mA)=a1g.y; AS(nb,kb+6,mA)=a1g.z; AS(nb,kb+7,mA)=a1g.w;
            BS(nb,kb+0,mA)=b0g.x; BS(nb,kb+1,mA)=b0g.y; BS(nb,kb+2,mA)=b0g.z; BS(nb,kb+3,mA)=b0g.w;
            BS(nb,kb+4,mA)=b1g.x; BS(nb,kb+5,mA)=b1g.y; BS(nb,kb+6,mA)=b1g.z; BS(nb,kb+7,mA)=b1g.w;
            __syncthreads();
            buf = nb;
        }
    }

    float4 bv0 = ((const float4*)bias)[(n0 >> 2) + tx * 2];
    float4 bv1 = ((const float4*)bias)[(n0 >> 2) + tx * 2 + 1];
    float4* out4 = (float4*)g_pre;
#pragma unroll
    for (int i = 0; i < 8; ++i) {
        const int m = m0 + ty * 8 + i;
        const size_t row = (size_t)dir * 32768 + m;
        float4 o0, o1;
        o0.x = acc[i][0] + bv0.x; o0.y = acc[i][1] + bv0.y;
        o0.z = acc[i][2] + bv0.z; o0.w = acc[i][3] + bv0.w;
        o1.x = acc[i][4] + bv1.x; o1.y = acc[i][5] + bv1.y;
        o1.z = acc[i][6] + bv1.z; o1.w = acc[i][7] + bv1.w;
        out4[row * 256 + (n0 >> 2) + tx * 2]     = o0;
        out4[row * 256 + (n0 >> 2) + tx * 2 + 1] = o1;
    }
#undef AS
#undef BS
#endif
}

// ---------------------------------------------------------------------------
// Kernel B: recurrence (byte-identical to the 3076us best)
// ---------------------------------------------------------------------------
#define SHT_P 9

__device__ __forceinline__ float fsigm(float x) {
    return __fdividef(1.f, 1.f + __expf(-x));
}
__device__ __forceinline__ float ftanh(float x) {
    float e = __expf(-2.f * fabsf(x));
    float r = __fdividef(1.f - e, 1.f + e);
    return copysignf(r, x);
}

__global__ void __launch_bounds__(512, 1)
lstm_rec_kernel(const float* __restrict__ Whh_f,
                const float* __restrict__ Whh_b) {
    const int bid = blockIdx.x;
    const int dir = bid >> 6;
    const int ug  = (bid >> 3) & 7;
    const int bg  = bid & 7;
    const int grp = dir * 8 + bg;
    const int tid = threadIdx.x;
    const int u   = tid >> 4;
    const int kq  = tid & 15;
    const int hu  = ug * 32 + u;
    const int bglob = bg * 8 + (kq & 7);

    const float* Whh = dir ? Whh_b : Whh_f;

    __shared__ __align__(16) float4 sHT[64 * SHT_P];

    const float4* whh4 = (const float4*)Whh;
    float4 w[4][4];
#pragma unroll
    for (int g = 0; g < 4; ++g)
#pragma unroll
        for (int j = 0; j < 4; ++j)
            w[g][j] = whh4[((size_t)(g * 256 + hu)) * 64 + kq + j * 16];

    const float4* gh4 = (const float4*)g_h;
    volatile unsigned* bar = &g_barg[grp * 32];

    const int t0 = dir ? 511 : 0;
    float4 pr = make_float4(0.f, 0.f, 0.f, 0.f);
    if (kq < 8) {
        size_t pb = ((size_t)dir * 32768 + (size_t)t0 * 64 + bglob) * 1024 + hu;
        pr.x = __ldcg(&g_pre[pb]);
        pr.y = __ldcg(&g_pre[pb + 256]);
        pr.z = __ldcg(&g_pre[pb + 512]);
        pr.w = __ldcg(&g_pre[pb + 768]);
    }

    float c = 0.f;
    const int bit2 = (kq >> 2) & 1;
    const int bit1 = (kq >> 1) & 1;
    const int bit0 = kq & 1;

    for (int it = 0; it < 512; ++it) {
        const int t = dir ? (511 - it) : it;

        {
            int b_ = tid >> 6, q = tid & 63;
            if (it == 0) {
                sHT[q * SHT_P + b_] = make_float4(0.f, 0.f, 0.f, 0.f);
            } else {
                const int tp = dir ? (t + 1) : (t - 1);
                size_t base = (((size_t)(dir * 512 + tp)) * 64 + bg * 8) * 64;
                sHT[q * SHT_P + b_] = __ldcg(&gh4[base + b_ * 64 + q]);
            }
        }
        __syncthreads();

        float4 prn = pr;
        if (it < 511 && kq < 8) {
            const int tn = dir ? (t - 1) : (t + 1);
            size_t pbn = ((size_t)dir * 32768 + (size_t)tn * 64 + bglob) * 1024 + hu;
            prn.x = __ldcg(&g_pre[pbn]);
            prn.y = __ldcg(&g_pre[pbn + 256]);
            prn.z = __ldcg(&g_pre[pbn + 512]);
            prn.w = __ldcg(&g_pre[pbn + 768]);
        }

        float acc[4][8];
#pragma unroll
        for (int g = 0; g < 4; ++g)
#pragma unroll
            for (int b = 0; b < 8; ++b) acc[g][b] = 0.f;

#pragma unroll
        for (int j = 0; j < 4; ++j) {
            const float4* row = &sHT[(kq + j * 16) * SHT_P];
#pragma unroll
            for (int b = 0; b < 8; ++b) {
                float4 h4 = row[b];
#pragma unroll
                for (int g = 0; g < 4; ++g) {
                    acc[g][b] = fmaf(w[g][j].x, h4.x,
                                fmaf(w[g][j].y, h4.y,
                                fmaf(w[g][j].z, h4.z,
                                fmaf(w[g][j].w, h4.w, acc[g][b]))));
                }
            }
        }

#pragma unroll
        for (int g = 0; g < 4; ++g)
#pragma unroll
            for (int b = 0; b < 8; ++b)
                acc[g][b] += __shfl_xor_sync(0xFFFFFFFFu, acc[g][b], 8);

        float r4[4][4];
#pragma unroll
        for (int g = 0; g < 4; ++g)
#pragma unroll
            for (int i = 0; i < 4; ++i) {
                float a0 = acc[g][i], a1 = acc[g][4 + i];
                float mine = bit2 ? a1 : a0;
                float oth  = bit2 ? a0 : a1;
                r4[g][i] = mine + __shfl_xor_sync(0xFFFFFFFFu, oth, 4);
            }
        float r2[4][2];
#pragma unroll
        for (int g = 0; g < 4; ++g)
#pragma unroll
            for (int i = 0; i < 2; ++i) {
                float a0 = r4[g][i], a1 = r4[g][2 + i];
                float mine = bit1 ? a1 : a0;
                float oth  = bit1 ? a0 : a1;
                r2[g][i] = mine + __shfl_xor_sync(0xFFFFFFFFu, oth, 2);
            }
        float s[4];
#pragma unroll
        for (int g = 0; g < 4; ++g) {
            float a0 = r2[g][0], a1 = r2[g][1];
            float mine = bit0 ? a1 : a0;
            float oth  = bit0 ? a0 : a1;
            s[g] = mine + __shfl_xor_sync(0xFFFFFFFFu, oth, 1);
        }

        if (kq < 8) {
            float gi = s[0] + pr.x;
            float gf = s[1] + pr.y;
            float gg = s[2] + pr.z;
            float go = s[3] + pr.w;

            float iv = fsigm(gi), fv = fsigm(gf), gv = ftanh(gg), ov = fsigm(go);
            c = fv * c + iv * gv;
            float hval = ov * ftanh(c);

            g_h[(((size_t)(dir * 512 + t)) * 64 + bglob) * 256 + hu] = hval;
        }

        __syncthreads();

        if (it < 511) {
            if (tid == 0) {
                __threadfence();
                atomicAdd((unsigned*)bar, 1u);
                unsigned target = 8u * (unsigned)(it + 1);
                while (*bar < target) { }
            }
            __syncthreads();
            __threadfence();
        }
        pr = prn;
    }
}

// ---------------------------------------------------------------------------
// Kernel C: logits (unchanged)
// ---------------------------------------------------------------------------
__global__ void logits_kernel(const float* __restrict__ Wout,
                              const float* __restrict__ bout) {
    const int t = blockIdx.x;
    __shared__ float sWo[10 * 512];
    __shared__ float sCH[64 * 65];
    __shared__ float sBo[10];

    const int tid = threadIdx.x;      // 640
    for (int idx = tid; idx < 5120; idx += 640) sWo[idx] = Wout[idx];
    if (tid < 10) sBo[tid] = bout[tid];

    const int n = tid / 64, bb = tid & 63;
    float acc = 0.f;
    const float4* gh4 = (const float4*)g_h;

    for (int ch = 0; ch < 8; ++ch) {
        __syncthreads();
        for (int idx = tid; idx < 1024; idx += 640) {
            int b_ = idx >> 4, q = idx & 15;
            int d = ch >> 2;
            int hid4 = (ch & 3) * 16 + q;
            float4 v = gh4[(((size_t)d * 512 + t) * 64 + b_) * 64 + hid4];
            float* dst = &sCH[(q * 4) * 65 + b_];
            dst[0]   = v.x;  dst[65]  = v.y;
            dst[130] = v.z;  dst[195] = v.w;
        }
        __syncthreads();
#pragma unroll 8
        for (int r = 0; r < 64; ++r)
            acc += sWo[n * 512 + ch * 64 + r] * sCH[r * 65 + bb];
    }
    g_logits[((size_t)t * 64 + bb) * 10 + n] = acc + sBo[n];
}

// ---------------------------------------------------------------------------
// Kernel D: Viterbi (unchanged, 63us)
// ---------------------------------------------------------------------------
__global__ void viterbi_kernel(const float* __restrict__ trans,
                               float* __restrict__ out) {
    const int tid  = threadIdx.x;
    const int w    = tid >> 5;
    const int lane = tid & 31;
    const int b    = blockIdx.x * 4 + w;

    __shared__ float         sLT[2][16][4][10];
    __shared__ float         sCur[4][32];
    __shared__ unsigned char bp[4][512][10];
    __shared__ float         tr[100];

    for (int i = tid; i < 100; i += 128) tr[i] = trans[i];

    const int bbase = blockIdx.x * 4;
    float stage[5];
#pragma unroll
    for (int s = 0; s < 5; ++s) {
        int idx = tid + s * 128;
        int t_off = idx / 40, rem = idx % 40;
        int b_off = rem / 10, k = rem % 10;
        stage[s] = g_logits[((size_t)(0 + t_off) * 64 + bbase + b_off) * 10 + k];
    }
#pragma unroll
    for (int s = 0; s < 5; ++s) {
        int idx = tid + s * 128;
        int t_off = idx / 40, rem = idx % 40;
        int b_off = rem / 10, k = rem % 10;
        sLT[0][t_off][b_off][k] = stage[s];
    }
    __syncthreads();

    float trc[10];
#pragma unroll
    for (int i = 0; i < 10; ++i) trc[i] = (lane < 10) ? tr[i * 10 + lane] : 0.f;

    float cur = (lane < 10) ? sLT[0][0][w][lane] : -1e30f;

    for (int cchunk = 0; cchunk < 32; ++cchunk) {
        const int buf = cchunk & 1;
        if (cchunk < 31) {
            const int tb = (cchunk + 1) * 16;
#pragma unroll
            for (int s = 0; s < 5; ++s) {
                int idx = tid + s * 128;
                int t_off = idx / 40, rem = idx % 40;
                int b_off = rem / 10, k = rem % 10;
                stage[s] = g_logits[((size_t)(tb + t_off) * 64 + bbase + b_off) * 10 + k];
            }
        }

        const int tstart = (cchunk == 0) ? 1 : 0;
#pragma unroll 4
        for (int ti = tstart; ti < 16; ++ti) {
            const int t = cchunk * 16 + ti;
            if (lane < 10) sCur[w][lane] = cur;
            __syncwarp();
            float best = sCur[w][0] + trc[0];
            int bi = 0;
#pragma unroll
            for (int i = 1; i < 10; ++i) {
                float v = sCur[w][i] + trc[i];
                if (v > best) { best = v; bi = i; }
            }
            __syncwarp();
            if (lane < 10) {
                cur = sLT[buf][ti][w][lane] + best;
                bp[w][t][lane] = (unsigned char)bi;
            }
        }

        if (cchunk < 31) {
            __syncthreads();
#pragma unroll
            for (int s = 0; s < 5; ++s) {
                int idx = tid + s * 128;
                int t_off = idx / 40, rem = idx % 40;
                int b_off = rem / 10, k = rem % 10;
                sLT[buf ^ 1][t_off][b_off][k] = stage[s];
            }
            __syncthreads();
        }
    }

    if (lane < 10) sCur[w][lane] = cur;
    __syncwarp();
    if (lane == 0) {
        float best = sCur[w][0]; int last = 0;
#pragma unroll
        for (int i = 1; i < 10; ++i)
            if (sCur[w][i] > best) { best = sCur[w][i]; last = i; }
        out[b] = best;
        float* po = out + 64 + (size_t)b * 512;
        int tag = last;
        po[511] = (float)tag;
        for (int t = 511; t >= 1; --t) {
            tag = bp[w][t][tag];
            po[t - 1] = (float)tag;
        }
    }
}

// ---------------------------------------------------------------------------
extern "C" void kernel_launch(void* const* d_in, const int* in_sizes, int n_in,
                              void* d_out, int out_size) {
    const int*   sent  = (const int*)  d_in[0];
    const float* emb   = (const float*)d_in[2];
    const float* Wih_f = (const float*)d_in[3];
    const float* Whh_f = (const float*)d_in[4];
    const float* b_f   = (const float*)d_in[5];
    const float* Wih_b = (const float*)d_in[6];
    const float* Whh_b = (const float*)d_in[7];
    const float* b_b   = (const float*)d_in[8];
    const float* W_out = (const float*)d_in[9];
    const float* b_out = (const float*)d_in[10];
    const float* trans = (const float*)d_in[11];
    float* out = (float*)d_out;

    cudaFuncSetAttribute(pregemm_kernel,
                         cudaFuncAttributeMaxDynamicSharedMemorySize, PG_SMEM);

    // launches: 1 init, 2 dummy, 3 dummy, 4 pregemm (ncu slot), 5 rec, 6 logits, 7 viterbi
    init_kernel<<<1, 512>>>();
    dummy_kernel<<<1, 32>>>();
    dummy_kernel<<<1, 32>>>();
    pregemm_kernel<<<dim3(8, 256, 2), 256, PG_SMEM>>>(sent, emb, Wih_f, b_f, Wih_b, b_b);
    lstm_rec_kernel<<<128, 512>>>(Whh_f, Whh_b);
    logits_kernel<<<512, 640>>>(W_out, b_out);
    viterbi_kernel<<<16, 128>>>(trans, out);
}

// round 17
// speedup vs baseline: 1.5521x; 1.1640x over previous
#include <cuda_runtime.h>
#include <cuda_bf16.h>
#include <math.h>

// Problem constants
#define BB   64
#define TT   512
#define EE   256
#define HH   256
#define G4   1024
#define KK   10

// tcgen05 is only legal in the sm_103a ('all-features') compilation pass.
#if defined(__CUDA_ARCH__) && defined(__CUDA_ARCH_FEAT_SM103_ALL)
#define PG_TC 1
#else
#define PG_TC 0
#endif

// -------- device scratch ----------------------------------------------------
__device__ float g_pre[2u * 32768u * 1024u];          // [dir][t*64+b][4H]
__device__ float g_h[2u * 512u * 64u * 256u];         // [dir][t][b][h]
__device__ float g_logits[512u * 64u * 10u];          // [t][b][k]
__device__ unsigned g_barg[16 * 32];                  // 16 group counters, 128B apart

__global__ void init_kernel() {
    int i = threadIdx.x;
    if (i < 16 * 32) g_barg[i] = 0u;
}
__global__ void dummy_kernel() {}

// ======================= tcgen05 / PTX helpers ==============================
__device__ __forceinline__ unsigned smem_u32(const void* p) {
    unsigned a;
    asm("{ .reg .u64 t; cvta.to.shared.u64 t, %1; cvt.u32.u64 %0, t; }"
        : "=r"(a) : "l"(p));
    return a;
}
#define SW128(off) ((off) ^ (((off) >> 3) & 0x70))

#if PG_TC
__device__ __forceinline__ unsigned elect_one() {
    unsigned pred;
    asm volatile("{\n\t.reg .pred p;\n\t"
                 "elect.sync _|p, 0xFFFFFFFF;\n\t"
                 "selp.b32 %0, 1, 0, p;\n\t}" : "=r"(pred));
    return pred;
}
static __device__ __forceinline__ unsigned long long make_desc(unsigned addr) {
    // SW128, Blackwell v1, SBO=64, LBO=1
    const unsigned long long base =
        (2ull << 61) | (1ull << 46) | (64ull << 32) | (1ull << 16);
    return base | ((unsigned long long)(addr >> 4) & 0x3FFFull);
}
__device__ __forceinline__ void tc_alloc(unsigned ctrl_addr, unsigned ncols) {
    asm volatile("tcgen05.alloc.cta_group::1.sync.aligned.shared::cta.b32 [%0], %1;"
                 :: "r"(ctrl_addr), "r"(ncols) : "memory");
}
__device__ __forceinline__ void tc_dealloc(unsigned tmem, unsigned ncols) {
    asm volatile("tcgen05.dealloc.cta_group::1.sync.aligned.b32 %0, %1;"
                 :: "r"(tmem), "r"(ncols));
}
__device__ __forceinline__ void mma_f16_ss(unsigned d_tmem,
                                           unsigned long long a_desc,
                                           unsigned long long b_desc,
                                           unsigned idesc, unsigned en) {
    asm volatile(
        "{\n\t.reg .pred p;\n\t"
        "setp.ne.u32 p, %4, 0;\n\t"
        "tcgen05.mma.cta_group::1.kind::f16 [%0], %1, %2, %3, {%5,%5,%5,%5}, p;\n\t}"
        :: "r"(d_tmem), "l"(a_desc), "l"(b_desc), "r"(idesc), "r"(en), "r"(0u)
        : "memory");
}
__device__ __forceinline__ void tc_commit(unsigned mbar) {
    asm volatile(
        "tcgen05.commit.cta_group::1.mbarrier::arrive::one.shared::cluster.b64 [%0];"
        :: "r"(mbar) : "memory");
}
__device__ __forceinline__ void mbar_init1(unsigned mbar) {
    asm volatile("mbarrier.init.shared.b64 [%0], 1;" :: "r"(mbar) : "memory");
}
__device__ __forceinline__ void mbar_inval(unsigned mbar) {
    asm volatile("mbarrier.inval.shared.b64 [%0];" :: "r"(mbar) : "memory");
}
__device__ __forceinline__ void mbar_wait(unsigned mbar, unsigned parity) {
    asm volatile(
        "{\n\t.reg .pred P1;\n\t"
        "WAIT_%=:\n\t"
        "mbarrier.try_wait.parity.acquire.cta.shared::cta.b64 P1, [%0], %1, 0x989680;\n\t"
        "@P1 bra.uni DONE_%=;\n\t"
        "bra.uni WAIT_%=;\n\t"
        "DONE_%=:\n\t}"
        :: "r"(mbar), "r"(parity) : "memory");
}
__device__ __forceinline__ void fence_async_smem() {
    asm volatile("fence.proxy.async.shared::cta;" ::: "memory");
}
__device__ __forceinline__ void tc_fence_after() {
    asm volatile("tcgen05.fence::after_thread_sync;" ::: "memory");
}
__device__ __forceinline__ void tc_fence_before() {
    asm volatile("tcgen05.fence::before_thread_sync;" ::: "memory");
}
__device__ __forceinline__ void tc_wait_ld() {
    asm volatile("tcgen05.wait::ld.sync.aligned;" ::: "memory");
}
#define TC_LD_X32(r, addr) \
    asm volatile( \
        "tcgen05.ld.sync.aligned.32x32b.x32.b32 " \
        "{%0,%1,%2,%3,%4,%5,%6,%7,%8,%9,%10,%11,%12,%13,%14,%15," \
        "%16,%17,%18,%19,%20,%21,%22,%23,%24,%25,%26,%27,%28,%29,%30,%31}, [%32];" \
        : "=r"((r)[0]),"=r"((r)[1]),"=r"((r)[2]),"=r"((r)[3]), \
          "=r"((r)[4]),"=r"((r)[5]),"=r"((r)[6]),"=r"((r)[7]), \
          "=r"((r)[8]),"=r"((r)[9]),"=r"((r)[10]),"=r"((r)[11]), \
          "=r"((r)[12]),"=r"((r)[13]),"=r"((r)[14]),"=r"((r)[15]), \
          "=r"((r)[16]),"=r"((r)[17]),"=r"((r)[18]),"=r"((r)[19]), \
          "=r"((r)[20]),"=r"((r)[21]),"=r"((r)[22]),"=r"((r)[23]), \
          "=r"((r)[24]),"=r"((r)[25]),"=r"((r)[26]),"=r"((r)[27]), \
          "=r"((r)[28]),"=r"((r)[29]),"=r"((r)[30]),"=r"((r)[31]) \
        : "r"(addr))

// idesc: dtype F32, atype/btype BF16, N=128, M=128 (cg1)
#define MMA_IDESC ((1u << 4) | (1u << 7) | (1u << 10) | (16u << 17) | (8u << 24))

// split fp32 -> 3 bf16 limbs (residuals exactly representable)
__device__ __forceinline__ void split3(float x, unsigned short& h,
                                       unsigned short& m, unsigned short& l) {
    __nv_bfloat16 bh = __float2bfloat16(x);
    float hf = __bfloat162float(bh);
    __nv_bfloat16 bm = __float2bfloat16(x - hf);
    float mf = __bfloat162float(bm);
    __nv_bfloat16 bl = __float2bfloat16(x - hf - mf);
    h = *(unsigned short*)&bh;
    m = *(unsigned short*)&bm;
    l = *(unsigned short*)&bl;
}
#endif  // PG_TC

// smem layout (tensor path): 2 sets x 6 tiles x 16KB, then ctrl
#define TILE_B   16384
#define CTRL_OFF (12 * TILE_B)
#define PG_SMEM  (CTRL_OFF + 128 + 1024)

// ---------------------------------------------------------------------------
// Kernel A: g_pre = emb[sent] @ Wih^T + bias.
//  PG_TC: tcgen05 bf16 multi-split, 6 limb passes, register-staged loads,
//         cross-chunk prefetch, double-buffered tiles w/ per-set mbarriers.
//  else:  fp32 register-blocked GEMM (proven 902us code).
// grid (8 n-tiles, 256 m-tiles, 2 dir), 256 threads, PG_SMEM dynamic smem.
// ---------------------------------------------------------------------------
__global__ void __launch_bounds__(256)
pregemm_kernel(const int* __restrict__ sent,
               const float* __restrict__ emb,
               const float* __restrict__ Wih_f,
               const float* __restrict__ b_f,
               const float* __restrict__ Wih_b,
               const float* __restrict__ b_b) {
    const int dir = blockIdx.z;
    const int n0  = blockIdx.x * 128;
    const int m0  = blockIdx.y * 128;
    const float* Wih  = dir ? Wih_b : Wih_f;
    const float* bias = dir ? b_b  : b_f;

    extern __shared__ char dsm[];
    const int tid = threadIdx.x;

#if PG_TC
    // ======================= TENSOR PATH =======================
    char* base = (char*)(((size_t)dsm + 1023) & ~(size_t)1023);
    const unsigned sb = smem_u32(base);
    unsigned ctrl = sb + CTRL_OFF;   // [ctrl] tmem ptr; [ctrl+8] mbarA; [ctrl+16] mbarB

    const int wid = tid >> 5;
    const int lid = tid & 31;

    __shared__ int toks[128];
    if (tid < 128) {
        int m = m0 + tid;
        toks[tid] = sent[(m & 63) * TT + (m >> 6)];
    }
    if (wid == 0) tc_alloc(ctrl, 128);
    if (tid == 0) { mbar_init1(ctrl + 8); mbar_init1(ctrl + 16); }
    __syncthreads();
    unsigned tmem;
    asm volatile("ld.shared.b32 %0, [%1];" : "=r"(tmem) : "r"(ctrl));

    // 6 limb passes: hh, hm, mh, mm, hl, lh  (ml/lm ~2^-27, dropped)
    const int passA[6] = {0, 0, 1, 1, 0, 2};
    const int passB[6] = {0, 1, 0, 1, 2, 0};

    // per-thread tile coordinates (fixed across chunks)
    const int rowT = tid >> 4;            // wrong for i>0; recompute in loop
    (void)rowT;

    float4 va[8], vb[8];
    // prefetch chunk 0
#pragma unroll
    for (int i = 0; i < 8; ++i) {
        int idx = i * 256 + tid;
        int row = idx >> 4, c4 = idx & 15;
        va[i] = *(const float4*)&emb[(size_t)toks[row] * 256 + c4 * 4];
        vb[i] = *(const float4*)&Wih[(size_t)(n0 + row) * 256 + c4 * 4];
    }

    for (int kc = 0; kc < 4; ++kc) {
        const int s = kc & 1;
        const unsigned mb = ctrl + 8 + s * 8;

        // set s was used by chunk kc-2; wait its commit (phase 0 of this mbar)
        if (kc >= 2) mbar_wait(mb, 0u);

        // ---- split + store chunk kc into set s ----
        char* tA0 = base + (s * 6 + 0) * TILE_B;
        char* tA1 = base + (s * 6 + 1) * TILE_B;
        char* tA2 = base + (s * 6 + 2) * TILE_B;
        char* tB0 = base + (s * 6 + 3) * TILE_B;
        char* tB1 = base + (s * 6 + 4) * TILE_B;
        char* tB2 = base + (s * 6 + 5) * TILE_B;
#pragma unroll
        for (int i = 0; i < 8; ++i) {
            int idx = i * 256 + tid;
            int row = idx >> 4, c4 = idx & 15;
            unsigned off = SW128((unsigned)(row * 128 + c4 * 8));
            unsigned short h[4], mm_[4], l[4];
            split3(va[i].x, h[0], mm_[0], l[0]);
            split3(va[i].y, h[1], mm_[1], l[1]);
            split3(va[i].z, h[2], mm_[2], l[2]);
            split3(va[i].w, h[3], mm_[3], l[3]);
            *(ushort4*)(tA0 + off) = make_ushort4(h[0], h[1], h[2], h[3]);
            *(ushort4*)(tA1 + off) = make_ushort4(mm_[0], mm_[1], mm_[2], mm_[3]);
            *(ushort4*)(tA2 + off) = make_ushort4(l[0], l[1], l[2], l[3]);
            split3(vb[i].x, h[0], mm_[0], l[0]);
            split3(vb[i].y, h[1], mm_[1], l[1]);
            split3(vb[i].z, h[2], mm_[2], l[2]);
            split3(vb[i].w, h[3], mm_[3], l[3]);
            *(ushort4*)(tB0 + off) = make_ushort4(h[0], h[1], h[2], h[3]);
            *(ushort4*)(tB1 + off) = make_ushort4(mm_[0], mm_[1], mm_[2], mm_[3]);
            *(ushort4*)(tB2 + off) = make_ushort4(l[0], l[1], l[2], l[3]);
        }

        // ---- prefetch chunk kc+1 (hidden under this chunk's MMA) ----
        if (kc < 3) {
            const int k0n = (kc + 1) * 64;
#pragma unroll
            for (int i = 0; i < 8; ++i) {
                int idx = i * 256 + tid;
                int row = idx >> 4, c4 = idx & 15;
                va[i] = *(const float4*)&emb[(size_t)toks[row] * 256 + k0n + c4 * 4];
                vb[i] = *(const float4*)&Wih[(size_t)(n0 + row) * 256 + k0n + c4 * 4];
            }
        }

        fence_async_smem();
        __syncthreads();

        // ---- issue 6 limb passes x 4 K-steps ----
        if (wid == 0 && elect_one()) {
            unsigned long long dA[3], dB[3];
#pragma unroll
            for (int q = 0; q < 3; ++q) {
                dA[q] = make_desc(sb + (s * 6 + q) * TILE_B);
                dB[q] = make_desc(sb + (s * 6 + 3 + q) * TILE_B);
            }
#pragma unroll
            for (int p = 0; p < 6; ++p) {
#pragma unroll
                for (int k = 0; k < 4; ++k) {
                    unsigned en = (kc == 0 && p == 0 && k == 0) ? 0u : 1u;
                    mma_f16_ss(tmem, dA[passA[p]] + k * 2,
                               dB[passB[p]] + k * 2, MMA_IDESC, en);
                }
            }
            tc_commit(mb);
        }
    }

    // final: wait phase 1 on both mbarriers (chunk 2 on A, chunk 3 on B)
    mbar_wait(ctrl + 8, 1u);
    mbar_wait(ctrl + 16, 1u);
    tc_fence_after();

    if (wid < 4) {
        const int m = m0 + wid * 32 + lid;
        const size_t rowbase = ((size_t)dir * 32768 + m) * 256 + (n0 >> 2);
        float4* out4 = (float4*)g_pre;
        const float4* bias4 = (const float4*)bias;
#pragma unroll
        for (int cb = 0; cb < 4; ++cb) {
            unsigned d[32];
            TC_LD_X32(d, tmem + cb * 32);
            tc_wait_ld();
#pragma unroll
            for (int q = 0; q < 8; ++q) {
                float4 bv = bias4[(n0 >> 2) + cb * 8 + q];
                float4 o;
                o.x = __uint_as_float(d[q * 4 + 0]) + bv.x;
                o.y = __uint_as_float(d[q * 4 + 1]) + bv.y;
                o.z = __uint_as_float(d[q * 4 + 2]) + bv.z;
                o.w = __uint_as_float(d[q * 4 + 3]) + bv.w;
                out4[rowbase + cb * 8 + q] = o;
            }
        }
        tc_fence_before();
    }
    __syncthreads();
    if (tid == 0) { mbar_inval(ctrl + 8); mbar_inval(ctrl + 16); }
    __syncthreads();
    if (wid == 0) tc_dealloc(tmem, 128);

#else
    // ======================= FP32 FALLBACK (902us code, smem in dsm) =======
    float* As = (float*)dsm;                     // [2][16][128]
    float* Bs = (float*)(dsm + 16384);           // [2][16][128]
    int*  toks = (int*)(dsm + 32768);            // [128]
#define AS(bf, k, m_) As[(bf) * 2048 + (k) * 128 + (m_)]
#define BS(bf, k, m_) Bs[(bf) * 2048 + (k) * 128 + (m_)]

    if (tid < 128) {
        int m = m0 + tid;
        toks[tid] = sent[(m & 63) * TT + (m >> 6)];
    }
    __syncthreads();

    const int mA   = tid & 127;
    const int half = tid >> 7;
    const int ty   = tid >> 4;
    const int tx   = tid & 15;

    const float4* emb4 = (const float4*)emb;
    const float4* w4   = (const float4*)Wih;

    const size_t arow = (size_t)toks[mA] * 64;
    const size_t brow = (size_t)(n0 + mA) * 64;

    float acc[8][8];
#pragma unroll
    for (int i = 0; i < 8; ++i)
#pragma unroll
        for (int j = 0; j < 8; ++j) acc[i][j] = 0.f;

    float4 a0g = emb4[arow + half * 2 + 0];
    float4 a1g = emb4[arow + half * 2 + 1];
    float4 b0g = w4  [brow + half * 2 + 0];
    float4 b1g = w4  [brow + half * 2 + 1];

    int buf = 0;
    {
        const int kb = half * 8;
        AS(0,kb+0,mA)=a0g.x; AS(0,kb+1,mA)=a0g.y; AS(0,kb+2,mA)=a0g.z; AS(0,kb+3,mA)=a0g.w;
        AS(0,kb+4,mA)=a1g.x; AS(0,kb+5,mA)=a1g.y; AS(0,kb+6,mA)=a1g.z; AS(0,kb+7,mA)=a1g.w;
        BS(0,kb+0,mA)=b0g.x; BS(0,kb+1,mA)=b0g.y; BS(0,kb+2,mA)=b0g.z; BS(0,kb+3,mA)=b0g.w;
        BS(0,kb+4,mA)=b1g.x; BS(0,kb+5,mA)=b1g.y; BS(0,kb+6,mA)=b1g.z; BS(0,kb+7,mA)=b1g.w;
    }
    __syncthreads();

    for (int kc = 0; kc < 16; ++kc) {
        if (kc < 15) {
            const size_t kq = (size_t)(kc + 1) * 4 + half * 2;
            a0g = emb4[arow + kq];  a1g = emb4[arow + kq + 1];
            b0g = w4  [brow + kq];  b1g = w4  [brow + kq + 1];
        }
#pragma unroll
        for (int kk = 0; kk < 16; ++kk) {
            float4 aA = *(const float4*)&AS(buf, kk, ty * 8);
            float4 aB = *(const float4*)&AS(buf, kk, ty * 8 + 4);
            float4 bA = *(const float4*)&BS(buf, kk, tx * 8);
            float4 bB = *(const float4*)&BS(buf, kk, tx * 8 + 4);
            float av[8] = {aA.x, aA.y, aA.z, aA.w, aB.x, aB.y, aB.z, aB.w};
            float bv[8] = {bA.x, bA.y, bA.z, bA.w, bB.x, bB.y, bB.z, bB.w};
#pragma unroll
            for (int i = 0; i < 8; ++i)
#pragma unroll
                for (int j = 0; j < 8; ++j)
                    acc[i][j] += av[i] * bv[j];
        }
        if (kc < 15) {
            const int nb = buf ^ 1;
            const int kb = half * 8;
            AS(nb,kb+0,mA)=a0g.x; AS(nb,kb+1,mA)=a0g.y; AS(nb,kb+2,mA)=a0g.z; AS(nb,kb+3,mA)=a0g.w;
            AS(nb,kb+4,mA)=a1g.x; AS(nb,kb+5,mA)=a1g.y; AS(nb,kb+6,mA)=a1g.z; AS(nb,kb+7,mA)=a1g.w;
            BS(nb,kb+0,mA)=b0g.x; BS(nb,kb+1,mA)=b0g.y; BS(nb,kb+2,mA)=b0g.z; BS(nb,kb+3,mA)=b0g.w;
            BS(nb,kb+4,mA)=b1g.x; BS(nb,kb+5,mA)=b1g.y; BS(nb,kb+6,mA)=b1g.z; BS(nb,kb+7,mA)=b1g.w;
            __syncthreads();
            buf = nb;
        }
    }

    float4 bv0 = ((const float4*)bias)[(n0 >> 2) + tx * 2];
    float4 bv1 = ((const float4*)bias)[(n0 >> 2) + tx * 2 + 1];
    float4* out4 = (float4*)g_pre;
#pragma unroll
    for (int i = 0; i < 8; ++i) {
        const int m = m0 + ty * 8 + i;
        const size_t row = (size_t)dir * 32768 + m;
        float4 o0, o1;
        o0.x = acc[i][0] + bv0.x; o0.y = acc[i][1] + bv0.y;
        o0.z = acc[i][2] + bv0.z; o0.w = acc[i][3] + bv0.w;
        o1.x = acc[i][4] + bv1.x; o1.y = acc[i][5] + bv1.y;
        o1.z = acc[i][6] + bv1.z; o1.w = acc[i][7] + bv1.w;
        out4[row * 256 + (n0 >> 2) + tx * 2]     = o0;
        out4[row * 256 + (n0 >> 2) + tx * 2 + 1] = o1;
    }
#undef AS
#undef BS
#endif
}

// ---------------------------------------------------------------------------
// Kernel B: recurrence (byte-identical to the 3076/2962us best)
// ---------------------------------------------------------------------------
#define SHT_P 9

__device__ __forceinline__ float fsigm(float x) {
    return __fdividef(1.f, 1.f + __expf(-x));
}
__device__ __forceinline__ float ftanh(float x) {
    float e = __expf(-2.f * fabsf(x));
    float r = __fdividef(1.f - e, 1.f + e);
    return copysignf(r, x);
}

__global__ void __launch_bounds__(512, 1)
lstm_rec_kernel(const float* __restrict__ Whh_f,
                const float* __restrict__ Whh_b) {
    const int bid = blockIdx.x;
    const int dir = bid >> 6;
    const int ug  = (bid >> 3) & 7;
    const int bg  = bid & 7;
    const int grp = dir * 8 + bg;
    const int tid = threadIdx.x;
    const int u   = tid >> 4;
    const int kq  = tid & 15;
    const int hu  = ug * 32 + u;
    const int bglob = bg * 8 + (kq & 7);

    const float* Whh = dir ? Whh_b : Whh_f;

    __shared__ __align__(16) float4 sHT[64 * SHT_P];

    const float4* whh4 = (const float4*)Whh;
    float4 w[4][4];
#pragma unroll
    for (int g = 0; g < 4; ++g)
#pragma unroll
        for (int j = 0; j < 4; ++j)
            w[g][j] = whh4[((size_t)(g * 256 + hu)) * 64 + kq + j * 16];

    const float4* gh4 = (const float4*)g_h;
    volatile unsigned* bar = &g_barg[grp * 32];

    const int t0 = dir ? 511 : 0;
    float4 pr = make_float4(0.f, 0.f, 0.f, 0.f);
    if (kq < 8) {
        size_t pb = ((size_t)dir * 32768 + (size_t)t0 * 64 + bglob) * 1024 + hu;
        pr.x = __ldcg(&g_pre[pb]);
        pr.y = __ldcg(&g_pre[pb + 256]);
        pr.z = __ldcg(&g_pre[pb + 512]);
        pr.w = __ldcg(&g_pre[pb + 768]);
    }

    float c = 0.f;
    const int bit2 = (kq >> 2) & 1;
    const int bit1 = (kq >> 1) & 1;
    const int bit0 = kq & 1;

    for (int it = 0; it < 512; ++it) {
        const int t = dir ? (511 - it) : it;

        {
            int b_ = tid >> 6, q = tid & 63;
            if (it == 0) {
                sHT[q * SHT_P + b_] = make_float4(0.f, 0.f, 0.f, 0.f);
            } else {
                const int tp = dir ? (t + 1) : (t - 1);
                size_t base = (((size_t)(dir * 512 + tp)) * 64 + bg * 8) * 64;
                sHT[q * SHT_P + b_] = __ldcg(&gh4[base + b_ * 64 + q]);
            }
        }
        __syncthreads();

        float4 prn = pr;
        if (it < 511 && kq < 8) {
            const int tn = dir ? (t - 1) : (t + 1);
            size_t pbn = ((size_t)dir * 32768 + (size_t)tn * 64 + bglob) * 1024 + hu;
            prn.x = __ldcg(&g_pre[pbn]);
            prn.y = __ldcg(&g_pre[pbn + 256]);
            prn.z = __ldcg(&g_pre[pbn + 512]);
            prn.w = __ldcg(&g_pre[pbn + 768]);
        }

        float acc[4][8];
#pragma unroll
        for (int g = 0; g < 4; ++g)
#pragma unroll
            for (int b = 0; b < 8; ++b) acc[g][b] = 0.f;

#pragma unroll
        for (int j = 0; j < 4; ++j) {
            const float4* row = &sHT[(kq + j * 16) * SHT_P];
#pragma unroll
            for (int b = 0; b < 8; ++b) {
                float4 h4 = row[b];
#pragma unroll
                for (int g = 0; g < 4; ++g) {
                    acc[g][b] = fmaf(w[g][j].x, h4.x,
                                fmaf(w[g][j].y, h4.y,
                                fmaf(w[g][j].z, h4.z,
                                fmaf(w[g][j].w, h4.w, acc[g][b]))));
                }
            }
        }

#pragma unroll
        for (int g = 0; g < 4; ++g)
#pragma unroll
            for (int b = 0; b < 8; ++b)
                acc[g][b] += __shfl_xor_sync(0xFFFFFFFFu, acc[g][b], 8);

        float r4[4][4];
#pragma unroll
        for (int g = 0; g < 4; ++g)
#pragma unroll
            for (int i = 0; i < 4; ++i) {
                float a0 = acc[g][i], a1 = acc[g][4 + i];
                float mine = bit2 ? a1 : a0;
                float oth  = bit2 ? a0 : a1;
                r4[g][i] = mine + __shfl_xor_sync(0xFFFFFFFFu, oth, 4);
            }
        float r2[4][2];
#pragma unroll
        for (int g = 0; g < 4; ++g)
#pragma unroll
            for (int i = 0; i < 2; ++i) {
                float a0 = r4[g][i], a1 = r4[g][2 + i];
                float mine = bit1 ? a1 : a0;
                float oth  = bit1 ? a0 : a1;
                r2[g][i] = mine + __shfl_xor_sync(0xFFFFFFFFu, oth, 2);
            }
        float s[4];
#pragma unroll
        for (int g = 0; g < 4; ++g) {
            float a0 = r2[g][0], a1 = r2[g][1];
            float mine = bit0 ? a1 : a0;
            float oth  = bit0 ? a0 : a1;
            s[g] = mine + __shfl_xor_sync(0xFFFFFFFFu, oth, 1);
        }

        if (kq < 8) {
            float gi = s[0] + pr.x;
            float gf = s[1] + pr.y;
            float gg = s[2] + pr.z;
            float go = s[3] + pr.w;

            float iv = fsigm(gi), fv = fsigm(gf), gv = ftanh(gg), ov = fsigm(go);
            c = fv * c + iv * gv;
            float hval = ov * ftanh(c);

            g_h[(((size_t)(dir * 512 + t)) * 64 + bglob) * 256 + hu] = hval;
        }

        __syncthreads();

        if (it < 511) {
            if (tid == 0) {
                __threadfence();
                atomicAdd((unsigned*)bar, 1u);
                unsigned target = 8u * (unsigned)(it + 1);
                while (*bar < target) { }
            }
            __syncthreads();
            __threadfence();
        }
        pr = prn;
    }
}

// ---------------------------------------------------------------------------
// Kernel C: logits (unchanged)
// ---------------------------------------------------------------------------
__global__ void logits_kernel(const float* __restrict__ Wout,
                              const float* __restrict__ bout) {
    const int t = blockIdx.x;
    __shared__ float sWo[10 * 512];
    __shared__ float sCH[64 * 65];
    __shared__ float sBo[10];

    const int tid = threadIdx.x;      // 640
    for (int idx = tid; idx < 5120; idx += 640) sWo[idx] = Wout[idx];
    if (tid < 10) sBo[tid] = bout[tid];

    const int n = tid / 64, bb = tid & 63;
    float acc = 0.f;
    const float4* gh4 = (const float4*)g_h;

    for (int ch = 0; ch < 8; ++ch) {
        __syncthreads();
        for (int idx = tid; idx < 1024; idx += 640) {
            int b_ = idx >> 4, q = idx & 15;
            int d = ch >> 2;
            int hid4 = (ch & 3) * 16 + q;
            float4 v = gh4[(((size_t)d * 512 + t) * 64 + b_) * 64 + hid4];
            float* dst = &sCH[(q * 4) * 65 + b_];
            dst[0]   = v.x;  dst[65]  = v.y;
            dst[130] = v.z;  dst[195] = v.w;
        }
        __syncthreads();
#pragma unroll 8
        for (int r = 0; r < 64; ++r)
            acc += sWo[n * 512 + ch * 64 + r] * sCH[r * 65 + bb];
    }
    g_logits[((size_t)t * 64 + bb) * 10 + n] = acc + sBo[n];
}

// ---------------------------------------------------------------------------
// Kernel D: Viterbi (unchanged, 63us)
// ---------------------------------------------------------------------------
__global__ void viterbi_kernel(const float* __restrict__ trans,
                               float* __restrict__ out) {
    const int tid  = threadIdx.x;
    const int w    = tid >> 5;
    const int lane = tid & 31;
    const int b    = blockIdx.x * 4 + w;

    __shared__ float         sLT[2][16][4][10];
    __shared__ float         sCur[4][32];
    __shared__ unsigned char bp[4][512][10];
    __shared__ float         tr[100];

    for (int i = tid; i < 100; i += 128) tr[i] = trans[i];

    const int bbase = blockIdx.x * 4;
    float stage[5];
#pragma unroll
    for (int s = 0; s < 5; ++s) {
        int idx = tid + s * 128;
        int t_off = idx / 40, rem = idx % 40;
        int b_off = rem / 10, k = rem % 10;
        stage[s] = g_logits[((size_t)(0 + t_off) * 64 + bbase + b_off) * 10 + k];
    }
#pragma unroll
    for (int s = 0; s < 5; ++s) {
        int idx = tid + s * 128;
        int t_off = idx / 40, rem = idx % 40;
        int b_off = rem / 10, k = rem % 10;
        sLT[0][t_off][b_off][k] = stage[s];
    }
    __syncthreads();

    float trc[10];
#pragma unroll
    for (int i = 0; i < 10; ++i) trc[i] = (lane < 10) ? tr[i * 10 + lane] : 0.f;

    float cur = (lane < 10) ? sLT[0][0][w][lane] : -1e30f;

    for (int cchunk = 0; cchunk < 32; ++cchunk) {
        const int buf = cchunk & 1;
        if (cchunk < 31) {
            const int tb = (cchunk + 1) * 16;
#pragma unroll
            for (int s = 0; s < 5; ++s) {
                int idx = tid + s * 128;
                int t_off = idx / 40, rem = idx % 40;
                int b_off = rem / 10, k = rem % 10;
                stage[s] = g_logits[((size_t)(tb + t_off) * 64 + bbase + b_off) * 10 + k];
            }
        }

        const int tstart = (cchunk == 0) ? 1 : 0;
#pragma unroll 4
        for (int ti = tstart; ti < 16; ++ti) {
            const int t = cchunk * 16 + ti;
            if (lane < 10) sCur[w][lane] = cur;
            __syncwarp();
            float best = sCur[w][0] + trc[0];
            int bi = 0;
#pragma unroll
            for (int i = 1; i < 10; ++i) {
                float v = sCur[w][i] + trc[i];
                if (v > best) { best = v; bi = i; }
            }
            __syncwarp();
            if (lane < 10) {
                cur = sLT[buf][ti][w][lane] + best;
                bp[w][t][lane] = (unsigned char)bi;
            }
        }

        if (cchunk < 31) {
            __syncthreads();
#pragma unroll
            for (int s = 0; s < 5; ++s) {
                int idx = tid + s * 128;
                int t_off = idx / 40, rem = idx % 40;
                int b_off = rem / 10, k = rem % 10;
                sLT[buf ^ 1][t_off][b_off][k] = stage[s];
            }
            __syncthreads();
        }
    }

    if (lane < 10) sCur[w][lane] = cur;
    __syncwarp();
    if (lane == 0) {
        float best = sCur[w][0]; int last = 0;
#pragma unroll
        for (int i = 1; i < 10; ++i)
            if (sCur[w][i] > best) { best = sCur[w][i]; last = i; }
        out[b] = best;
        float* po = out + 64 + (size_t)b * 512;
        int tag = last;
        po[511] = (float)tag;
        for (int t = 511; t >= 1; --t) {
            tag = bp[w][t][tag];
            po[t - 1] = (float)tag;
        }
    }
}

// ---------------------------------------------------------------------------
extern "C" void kernel_launch(void* const* d_in, const int* in_sizes, int n_in,
                              void* d_out, int out_size) {
    const int*   sent  = (const int*)  d_in[0];
    const float* emb   = (const float*)d_in[2];
    const float* Wih_f = (const float*)d_in[3];
    const float* Whh_f = (const float*)d_in[4];
    const float* b_f   = (const float*)d_in[5];
    const float* Wih_b = (const float*)d_in[6];
    const float* Whh_b = (const float*)d_in[7];
    const float* b_b   = (const float*)d_in[8];
    const float* W_out = (const float*)d_in[9];
    const float* b_out = (const float*)d_in[10];
    const float* trans = (const float*)d_in[11];
    float* out = (float*)d_out;

    cudaFuncSetAttribute(pregemm_kernel,
                         cudaFuncAttributeMaxDynamicSharedMemorySize, PG_SMEM);

    // launches: 1 init, 2 dummy, 3 dummy, 4 pregemm (ncu slot), 5 rec, 6 logits, 7 viterbi
    init_kernel<<<1, 512>>>();
    dummy_kernel<<<1, 32>>>();
    dummy_kernel<<<1, 32>>>();
    pregemm_kernel<<<dim3(8, 256, 2), 256, PG_SMEM>>>(sent, emb, Wih_f, b_f, Wih_b, b_b);
    lstm_rec_kernel<<<128, 512>>>(Whh_f, Whh_b);
    logits_kernel<<<512, 640>>>(W_out, b_out);
    viterbi_kernel<<<16, 128>>>(trans, out);
}